// round 1
// baseline (speedup 1.0000x reference)
#include <cuda_runtime.h>
#include <cuda_bf16.h>
#include <math.h>

// Problem constants
#define BB   4
#define TT   1024
#define CC   1024
#define HH   16
#define DD   64
#define BT   (BB*TT)          // 4096

// Scratch (allocation-free rule: __device__ globals)
__device__ float g_Q[BT * CC];
__device__ float g_K[BT * CC];
__device__ float g_V[BT * CC];
__device__ float g_Y[BT * CC];

// ---------------------------------------------------------------------------
// C[M,N] = A[M,K] @ B[N,K]^T   (both operands K-contiguous, row-major)
// 128x128 tile, BK=8, 256 threads, 8x8 microtile, float4 everywhere.
// ---------------------------------------------------------------------------
__global__ __launch_bounds__(256, 2)
void sgemm_nt(const float* __restrict__ A, const float* __restrict__ B,
              float* __restrict__ C, int M, int N, int K)
{
    __shared__ float As[8][128];
    __shared__ float Bs[8][128];

    const int tid = threadIdx.x;
    const int lr = tid >> 1;            // 0..127  (load row)
    const int lc = (tid & 1) << 2;      // 0 or 4  (load k-col, float4)
    const int tx = tid & 15;            // 0..15
    const int ty = tid >> 4;            // 0..15

    const float* Ap = A + ((size_t)(blockIdx.y * 128 + lr)) * K + lc;
    const float* Bp = B + ((size_t)(blockIdx.x * 128 + lr)) * K + lc;

    float acc[8][8];
    #pragma unroll
    for (int i = 0; i < 8; i++)
        #pragma unroll
        for (int j = 0; j < 8; j++) acc[i][j] = 0.f;

    for (int k0 = 0; k0 < K; k0 += 8) {
        float4 a  = *(const float4*)(Ap + k0);
        float4 b4 = *(const float4*)(Bp + k0);
        __syncthreads();
        As[lc + 0][lr] = a.x;  As[lc + 1][lr] = a.y;
        As[lc + 2][lr] = a.z;  As[lc + 3][lr] = a.w;
        Bs[lc + 0][lr] = b4.x; Bs[lc + 1][lr] = b4.y;
        Bs[lc + 2][lr] = b4.z; Bs[lc + 3][lr] = b4.w;
        __syncthreads();

        #pragma unroll
        for (int kk = 0; kk < 8; kk++) {
            float ra[8], rb[8];
            *(float4*)(ra)     = *(const float4*)&As[kk][ty * 4];
            *(float4*)(ra + 4) = *(const float4*)&As[kk][64 + ty * 4];
            *(float4*)(rb)     = *(const float4*)&Bs[kk][tx * 4];
            *(float4*)(rb + 4) = *(const float4*)&Bs[kk][64 + tx * 4];
            #pragma unroll
            for (int i = 0; i < 8; i++)
                #pragma unroll
                for (int j = 0; j < 8; j++)
                    acc[i][j] += ra[i] * rb[j];
        }
    }

    #pragma unroll
    for (int ih = 0; ih < 2; ih++) {
        #pragma unroll
        for (int r = 0; r < 4; r++) {
            int row = blockIdx.y * 128 + ih * 64 + ty * 4 + r;
            #pragma unroll
            for (int jh = 0; jh < 2; jh++) {
                int col = blockIdx.x * 128 + jh * 64 + tx * 4;
                float4 v = make_float4(acc[ih * 4 + r][jh * 4 + 0],
                                       acc[ih * 4 + r][jh * 4 + 1],
                                       acc[ih * 4 + r][jh * 4 + 2],
                                       acc[ih * 4 + r][jh * 4 + 3]);
                *(float4*)(C + (size_t)row * N + col) = v;
            }
        }
    }
}

// ---------------------------------------------------------------------------
// Attention: one block per (b, h, 32-query tile). 256 threads.
// Full 32x1024 score strip in smem. Each warp owns 4 query rows end-to-end
// (scores -> bias -> softmax -> attn write -> PV), so sS is warp-private.
// smem: sS[32][1024] + sQ[32][65] + sKV[64][65]  = 156,032 bytes
// ---------------------------------------------------------------------------
__global__ __launch_bounds__(256, 1)
void attn_kernel(const float* __restrict__ Q, const float* __restrict__ Km,
                 const float* __restrict__ V, float* __restrict__ attn,
                 float* __restrict__ Y)
{
    extern __shared__ float sm[];
    float* sS = sm;                    // 32*1024
    float* sQ = sS + 32 * 1024;        // 32*65
    float* sK = sQ + 32 * 65;          // 64*65

    const int tid  = threadIdx.x;
    const int lane = tid & 31;
    const int warp = tid >> 5;         // 0..7
    const int qb   = blockIdx.x * 32;
    const int h    = blockIdx.y;
    const int b    = blockIdx.z;

    const float scale = 0.125f;                        // 1/sqrt(64)
    const float slope = exp2f(-0.5f * (float)(h + 1)); // ALiBi slope

    // ---- load Q tile [32 x 64] into sQ (padded stride 65) ----
    {
        const float* Qb = Q + ((size_t)(b * TT + qb)) * CC + h * DD;
        for (int i = tid; i < 32 * 16; i += 256) {
            int r = i >> 4, c4 = (i & 15) << 2;
            float4 v = *(const float4*)(Qb + (size_t)r * CC + c4);
            float* dst = sQ + r * 65 + c4;
            dst[0] = v.x; dst[1] = v.y; dst[2] = v.z; dst[3] = v.w;
        }
    }

    const int tk = lane;               // key lane
    const int tq = warp;               // 4 query rows per warp

    // ---- scores: sS[q][k] = (Q.K)*scale - slope*|q-k| ----
    for (int kc = 0; kc < TT; kc += 64) {
        __syncthreads();               // protect sK reuse (+first-iter sQ)
        const float* Kb = Km + ((size_t)(b * TT + kc)) * CC + h * DD;
        for (int i = tid; i < 64 * 16; i += 256) {
            int r = i >> 4, c4 = (i & 15) << 2;
            float4 v = *(const float4*)(Kb + (size_t)r * CC + c4);
            float* dst = sK + r * 65 + c4;
            dst[0] = v.x; dst[1] = v.y; dst[2] = v.z; dst[3] = v.w;
        }
        __syncthreads();

        float acc0[4], acc1[4];
        #pragma unroll
        for (int i = 0; i < 4; i++) { acc0[i] = 0.f; acc1[i] = 0.f; }

        #pragma unroll 8
        for (int kd = 0; kd < 64; kd++) {
            float k0 = sK[tk * 65 + kd];
            float k1 = sK[(tk + 32) * 65 + kd];
            #pragma unroll
            for (int i = 0; i < 4; i++) {
                float qv = sQ[(tq * 4 + i) * 65 + kd];  // warp-broadcast
                acc0[i] += qv * k0;
                acc1[i] += qv * k1;
            }
        }
        #pragma unroll
        for (int i = 0; i < 4; i++) {
            int qg = qb + tq * 4 + i;
            int k0 = kc + tk, k1 = kc + tk + 32;
            sS[(tq * 4 + i) * 1024 + k0] = acc0[i] * scale - slope * fabsf((float)(qg - k0));
            sS[(tq * 4 + i) * 1024 + k1] = acc1[i] * scale - slope * fabsf((float)(qg - k1));
        }
    }
    __syncthreads();

    // ---- softmax per row (each warp: its own 4 rows), write attn ----
    const size_t attn_base = (((size_t)(b * HH + h)) * TT + qb) * TT;
    #pragma unroll
    for (int rr = 0; rr < 4; rr++) {
        int q = warp * 4 + rr;
        float* row = sS + q * 1024;
        float m = -1e30f;
        #pragma unroll 8
        for (int it = 0; it < 32; it++) m = fmaxf(m, row[it * 32 + lane]);
        #pragma unroll
        for (int off = 16; off; off >>= 1) m = fmaxf(m, __shfl_xor_sync(~0u, m, off));
        float s = 0.f;
        #pragma unroll 8
        for (int it = 0; it < 32; it++) {
            float e = __expf(row[it * 32 + lane] - m);
            row[it * 32 + lane] = e;
            s += e;
        }
        #pragma unroll
        for (int off = 16; off; off >>= 1) s += __shfl_xor_sync(~0u, s, off);
        float inv = 1.0f / s;
        float* out = attn + attn_base + (size_t)q * 1024;
        #pragma unroll
        for (int it = 0; it < 8; it++) {
            int c = it * 128 + lane * 4;
            float4 v = *(float4*)(row + c);
            v.x *= inv; v.y *= inv; v.z *= inv; v.w *= inv;
            *(float4*)(row + c) = v;
            *(float4*)(out + c) = v;
        }
    }

    // ---- PV: y[q][d] = sum_k P[q][k] * V[k][d] ----
    const int td = lane;
    float yacc0[4], yacc1[4];
    #pragma unroll
    for (int i = 0; i < 4; i++) { yacc0[i] = 0.f; yacc1[i] = 0.f; }

    for (int kc = 0; kc < TT; kc += 64) {
        __syncthreads();               // protect sK reuse (covers post-softmax too)
        const float* Vb = V + ((size_t)(b * TT + kc)) * CC + h * DD;
        for (int i = tid; i < 64 * 16; i += 256) {
            int r = i >> 4, c4 = (i & 15) << 2;
            float4 v = *(const float4*)(Vb + (size_t)r * CC + c4);
            float* dst = sK + r * 65 + c4;
            dst[0] = v.x; dst[1] = v.y; dst[2] = v.z; dst[3] = v.w;
        }
        __syncthreads();

        #pragma unroll 8
        for (int kk = 0; kk < 64; kk++) {
            float v0 = sK[kk * 65 + td];
            float v1 = sK[kk * 65 + td + 32];
            #pragma unroll
            for (int i = 0; i < 4; i++) {
                float p = sS[(tq * 4 + i) * 1024 + kc + kk];  // warp-broadcast
                yacc0[i] += p * v0;
                yacc1[i] += p * v1;
            }
        }
    }

    #pragma unroll
    for (int i = 0; i < 4; i++) {
        int qg = qb + tq * 4 + i;
        float* yp = Y + ((size_t)(b * TT + qg)) * CC + h * DD;
        yp[td]      = yacc0[i];
        yp[td + 32] = yacc1[i];
    }
}

// ---------------------------------------------------------------------------
// kernel_launch: QKV proj -> attention (+attn write) -> output proj
// Output layout: d_out = [ y (B*T*C) | attn (B*H*T*T) ]
// ---------------------------------------------------------------------------
extern "C" void kernel_launch(void* const* d_in, const int* in_sizes, int n_in,
                              void* d_out, int out_size)
{
    const float* x  = (const float*)d_in[0];
    const float* Wq = (const float*)d_in[1];
    const float* Wk = (const float*)d_in[2];
    const float* Wv = (const float*)d_in[3];
    const float* Wp = (const float*)d_in[4];

    float* out      = (float*)d_out;
    float* y_out    = out;
    float* attn_out = out + (size_t)BB * TT * CC;

    float *Qp, *Kp, *Vp, *Yp;
    cudaGetSymbolAddress((void**)&Qp, g_Q);
    cudaGetSymbolAddress((void**)&Kp, g_K);
    cudaGetSymbolAddress((void**)&Vp, g_V);
    cudaGetSymbolAddress((void**)&Yp, g_Y);

    dim3 gg(CC / 128, BT / 128);       // (8, 32)
    sgemm_nt<<<gg, 256>>>(x, Wq, Qp, BT, CC, CC);
    sgemm_nt<<<gg, 256>>>(x, Wk, Kp, BT, CC, CC);
    sgemm_nt<<<gg, 256>>>(x, Wv, Vp, BT, CC, CC);

    size_t smem = (size_t)(32 * 1024 + 32 * 65 + 64 * 65) * sizeof(float);
    cudaFuncSetAttribute(attn_kernel, cudaFuncAttributeMaxDynamicSharedMemorySize, (int)smem);
    attn_kernel<<<dim3(TT / 32, HH, BB), 256, smem>>>(Qp, Kp, Vp, attn_out, Yp);

    sgemm_nt<<<gg, 256>>>(Yp, Wp, y_out, BT, CC, CC);
}

// round 2
// speedup vs baseline: 2.9199x; 2.9199x over previous
#include <cuda_runtime.h>
#include <math.h>
#include <stdint.h>

#define BB   4
#define TT   1024
#define CC   1024
#define HH   16
#define DD   64
#define BT   (BB*TT)          // 4096

// Scratch (allocation-free rule: __device__ globals)
__device__ float g_Q[BT * CC];
__device__ float g_K[BT * CC];
__device__ float g_V[BT * CC];
__device__ float g_Y[BT * CC];

// ---------------------------------------------------------------------------
// helpers
// ---------------------------------------------------------------------------
__device__ __forceinline__ float tf32r(float x) {
    uint32_t u;
    asm("cvt.rna.tf32.f32 %0, %1;" : "=r"(u) : "f"(x));
    return __uint_as_float(u);
}
__device__ __forceinline__ float4 tf32r4(float4 v) {
    float4 w;
    w.x = tf32r(v.x); w.y = tf32r(v.y); w.z = tf32r(v.z); w.w = tf32r(v.w);
    return w;
}
__device__ __forceinline__ uint32_t bitsf(float x) { return __float_as_uint(x); }

__device__ __forceinline__ void mma_tf32(float* c, const uint32_t* a, const uint32_t* b) {
    asm volatile(
        "mma.sync.aligned.m16n8k8.row.col.f32.tf32.tf32.f32 "
        "{%0,%1,%2,%3}, {%4,%5,%6,%7}, {%8,%9}, {%0,%1,%2,%3};"
        : "+f"(c[0]), "+f"(c[1]), "+f"(c[2]), "+f"(c[3])
        : "r"(a[0]), "r"(a[1]), "r"(a[2]), "r"(a[3]), "r"(b[0]), "r"(b[1]));
}

// ---------------------------------------------------------------------------
// C[M,N] = A[M,K] @ W[N,K]^T  in TF32 tensor cores.
// 128x128 tile, BK=32, 512 threads (16 warps, 4x4 warp grid, 32x32 warp tile),
// double-buffered smem (stride 36 -> conflict-free fragment LDS).
// blockIdx.z selects one of up to 3 (W, C) pairs (QKV fusion).
// ---------------------------------------------------------------------------
#define GS 36
__global__ __launch_bounds__(512, 1)
void gemm_tf32_nt(const float* __restrict__ A,
                  const float* __restrict__ W0, const float* __restrict__ W1,
                  const float* __restrict__ W2,
                  float* __restrict__ C0, float* __restrict__ C1,
                  float* __restrict__ C2,
                  int M, int N, int K)
{
    const float* Bw = (blockIdx.z == 0) ? W0 : (blockIdx.z == 1 ? W1 : W2);
    float*       C  = (blockIdx.z == 0) ? C0 : (blockIdx.z == 1 ? C1 : C2);

    extern __shared__ float sm[];
    float* As = sm;                 // [2][128][GS]
    float* Bs = sm + 2 * 128 * GS;  // [2][128][GS]

    const int tid  = threadIdx.x;
    const int lane = tid & 31;
    const int warp = tid >> 5;            // 0..15
    const int wm   = (warp & 3) * 32;     // warp m offset in tile
    const int wn   = (warp >> 2) * 32;    // warp n offset in tile

    const int lr = tid >> 3;              // 0..63 (load row)
    const int lc = (tid & 7) << 2;        // k-col (float4)

    const float* Ap = A  + (size_t)(blockIdx.y * 128 + lr) * K + lc;
    const float* Bp = Bw + (size_t)(blockIdx.x * 128 + lr) * K + lc;

    float acc[2][4][4];
    #pragma unroll
    for (int i = 0; i < 2; i++)
        #pragma unroll
        for (int j = 0; j < 4; j++)
            #pragma unroll
            for (int k = 0; k < 4; k++) acc[i][j][k] = 0.f;

    float4 ra0, ra1, rb0, rb1;
    // prologue: tile 0
    ra0 = *(const float4*)(Ap);
    ra1 = *(const float4*)(Ap + (size_t)64 * K);
    rb0 = *(const float4*)(Bp);
    rb1 = *(const float4*)(Bp + (size_t)64 * K);
    *(float4*)(As + lr * GS + lc)        = tf32r4(ra0);
    *(float4*)(As + (lr + 64) * GS + lc) = tf32r4(ra1);
    *(float4*)(Bs + lr * GS + lc)        = tf32r4(rb0);
    *(float4*)(Bs + (lr + 64) * GS + lc) = tf32r4(rb1);
    __syncthreads();

    const int NT = K / 32;
    int buf = 0;
    for (int kt = 0; kt < NT; kt++) {
        if (kt + 1 < NT) {
            int ko = (kt + 1) * 32;
            ra0 = *(const float4*)(Ap + ko);
            ra1 = *(const float4*)(Ap + (size_t)64 * K + ko);
            rb0 = *(const float4*)(Bp + ko);
            rb1 = *(const float4*)(Bp + (size_t)64 * K + ko);
        }
        const float* Ab = As + buf * 128 * GS;
        const float* Bb = Bs + buf * 128 * GS;

        #pragma unroll
        for (int ks = 0; ks < 4; ks++) {
            const int k0 = ks * 8 + (lane & 3);
            uint32_t af[2][4], bf[4][2];
            #pragma unroll
            for (int mt = 0; mt < 2; mt++) {
                int r = wm + mt * 16 + (lane >> 2);
                af[mt][0] = bitsf(Ab[r * GS + k0]);
                af[mt][1] = bitsf(Ab[(r + 8) * GS + k0]);
                af[mt][2] = bitsf(Ab[r * GS + k0 + 4]);
                af[mt][3] = bitsf(Ab[(r + 8) * GS + k0 + 4]);
            }
            #pragma unroll
            for (int nt = 0; nt < 4; nt++) {
                int n = wn + nt * 8 + (lane >> 2);
                bf[nt][0] = bitsf(Bb[n * GS + k0]);
                bf[nt][1] = bitsf(Bb[n * GS + k0 + 4]);
            }
            #pragma unroll
            for (int mt = 0; mt < 2; mt++)
                #pragma unroll
                for (int nt = 0; nt < 4; nt++)
                    mma_tf32(acc[mt][nt], af[mt], bf[nt]);
        }

        if (kt + 1 < NT) {
            float* Ad = As + (buf ^ 1) * 128 * GS;
            float* Bd = Bs + (buf ^ 1) * 128 * GS;
            *(float4*)(Ad + lr * GS + lc)        = tf32r4(ra0);
            *(float4*)(Ad + (lr + 64) * GS + lc) = tf32r4(ra1);
            *(float4*)(Bd + lr * GS + lc)        = tf32r4(rb0);
            *(float4*)(Bd + (lr + 64) * GS + lc) = tf32r4(rb1);
        }
        __syncthreads();
        buf ^= 1;
    }

    #pragma unroll
    for (int mt = 0; mt < 2; mt++) {
        int r0 = blockIdx.y * 128 + wm + mt * 16 + (lane >> 2);
        #pragma unroll
        for (int nt = 0; nt < 4; nt++) {
            int c0 = blockIdx.x * 128 + wn + nt * 8 + (lane & 3) * 2;
            *(float2*)&C[(size_t)r0 * N + c0] =
                make_float2(acc[mt][nt][0], acc[mt][nt][1]);
            *(float2*)&C[(size_t)(r0 + 8) * N + c0] =
                make_float2(acc[mt][nt][2], acc[mt][nt][3]);
        }
    }
}

// ---------------------------------------------------------------------------
// Attention: one block per (b, h, 32-query tile). 256 threads, 8 warps.
// QK^T and PV via TF32 MMA; softmax + ALiBi + attn-write fp32 SIMT.
// Score strip sS[32][1028] in smem (stride ≡ 4 mod 32 -> conflict-free frags).
// ---------------------------------------------------------------------------
#define SSST 1028
#define SQST 68
#define SVST 72
__global__ __launch_bounds__(256, 1)
void attn_kernel(const float* __restrict__ Q, const float* __restrict__ Km,
                 const float* __restrict__ V, float* __restrict__ attn,
                 float* __restrict__ Y)
{
    extern __shared__ float sm[];
    float* sS  = sm;                      // 32 * 1028
    float* sQ  = sS + 32 * SSST;          // 32 * 68   (tf32 Q)
    float* sKV = sQ + 32 * SQST;          // 64 * 72   (tf32 K or V chunk)

    const int tid  = threadIdx.x;
    const int lane = tid & 31;
    const int warp = tid >> 5;            // 0..7
    const int qb   = blockIdx.x * 32;
    const int h    = blockIdx.y;
    const int b    = blockIdx.z;

    const float scale = 0.125f;                         // 1/sqrt(64)
    const float slope = exp2f(-0.5f * (float)(h + 1));  // ALiBi slope

    const int mt = warp & 1;              // which 16 query rows
    const int wn = warp >> 1;             // 16-wide column chunk

    // ---- load Q tile [32 x 64] -> sQ (tf32) ----
    {
        const float* Qb = Q + ((size_t)(b * TT + qb)) * CC + h * DD;
        #pragma unroll
        for (int p = 0; p < 2; p++) {
            int i = p * 256 + tid;
            int r = i >> 4, c4 = (i & 15) << 2;
            float4 v = *(const float4*)(Qb + (size_t)r * CC + c4);
            *(float4*)(sQ + r * SQST + c4) = tf32r4(v);
        }
    }

    // ---- scores via MMA: sS[q][k] = (Q.K)*scale - slope*|q-k| ----
    for (int kc = 0; kc < TT; kc += 64) {
        __syncthreads();
        const float* Kb = Km + ((size_t)(b * TT + kc)) * CC + h * DD;
        #pragma unroll
        for (int p = 0; p < 4; p++) {
            int i = p * 256 + tid;
            int r = i >> 4, c4 = (i & 15) << 2;
            float4 v = *(const float4*)(Kb + (size_t)r * CC + c4);
            *(float4*)(sKV + r * SQST + c4) = tf32r4(v);
        }
        __syncthreads();

        float c[2][4];
        #pragma unroll
        for (int nt = 0; nt < 2; nt++)
            #pragma unroll
            for (int i = 0; i < 4; i++) c[nt][i] = 0.f;

        #pragma unroll
        for (int ks = 0; ks < 8; ks++) {
            const int k0 = ks * 8 + (lane & 3);
            uint32_t a[4], bf[2][2];
            int r = mt * 16 + (lane >> 2);
            a[0] = bitsf(sQ[r * SQST + k0]);
            a[1] = bitsf(sQ[(r + 8) * SQST + k0]);
            a[2] = bitsf(sQ[r * SQST + k0 + 4]);
            a[3] = bitsf(sQ[(r + 8) * SQST + k0 + 4]);
            #pragma unroll
            for (int nt = 0; nt < 2; nt++) {
                int n = wn * 16 + nt * 8 + (lane >> 2);
                bf[nt][0] = bitsf(sKV[n * SQST + k0]);
                bf[nt][1] = bitsf(sKV[n * SQST + k0 + 4]);
            }
            mma_tf32(c[0], a, bf[0]);
            mma_tf32(c[1], a, bf[1]);
        }

        #pragma unroll
        for (int nt = 0; nt < 2; nt++) {
            #pragma unroll
            for (int i = 0; i < 4; i++) {
                int r  = mt * 16 + (lane >> 2) + ((i >> 1) << 3);
                int cl = wn * 16 + nt * 8 + (lane & 3) * 2 + (i & 1);
                float qg = (float)(qb + r);
                float kg = (float)(kc + cl);
                sS[r * SSST + kc + cl] = c[nt][i] * scale - slope * fabsf(qg - kg);
            }
        }
    }
    __syncthreads();

    // ---- softmax per row (warp owns rows warp*4..+3), write attn (fp32),
    //      store tf32 P back into sS for the PV MMA ----
    const size_t attn_base = (((size_t)(b * HH + h)) * TT + qb) * TT;
    #pragma unroll
    for (int rr = 0; rr < 4; rr++) {
        int q = warp * 4 + rr;
        float* row = sS + q * SSST;
        float m = -1e30f;
        #pragma unroll 8
        for (int it = 0; it < 32; it++) m = fmaxf(m, row[it * 32 + lane]);
        #pragma unroll
        for (int off = 16; off; off >>= 1) m = fmaxf(m, __shfl_xor_sync(~0u, m, off));
        float s = 0.f;
        #pragma unroll 8
        for (int it = 0; it < 32; it++) {
            float e = __expf(row[it * 32 + lane] - m);
            row[it * 32 + lane] = e;
            s += e;
        }
        #pragma unroll
        for (int off = 16; off; off >>= 1) s += __shfl_xor_sync(~0u, s, off);
        float inv = 1.0f / s;
        float* out = attn + attn_base + (size_t)q * TT;
        #pragma unroll
        for (int it = 0; it < 8; it++) {
            int cx = it * 128 + lane * 4;
            float4 v = *(float4*)(row + cx);
            v.x *= inv; v.y *= inv; v.z *= inv; v.w *= inv;
            *(float4*)(out + cx) = v;          // fp32 attn output
            *(float4*)(row + cx) = tf32r4(v);  // tf32 P for PV
        }
    }

    // ---- PV via MMA: y[32][64] = P @ V ----
    float yc[2][4];
    #pragma unroll
    for (int nt = 0; nt < 2; nt++)
        #pragma unroll
        for (int i = 0; i < 4; i++) yc[nt][i] = 0.f;

    for (int kc = 0; kc < TT; kc += 64) {
        __syncthreads();
        const float* Vb = V + ((size_t)(b * TT + kc)) * CC + h * DD;
        #pragma unroll
        for (int p = 0; p < 4; p++) {
            int i = p * 256 + tid;
            int r = i >> 4, c4 = (i & 15) << 2;
            float4 v = *(const float4*)(Vb + (size_t)r * CC + c4);
            *(float4*)(sKV + r * SVST + c4) = tf32r4(v);   // stride 72
        }
        __syncthreads();

        #pragma unroll
        for (int ks = 0; ks < 8; ks++) {
            const int k0 = ks * 8;
            uint32_t a[4], bf[2][2];
            int r = mt * 16 + (lane >> 2);
            int kcol = kc + k0 + (lane & 3);
            a[0] = bitsf(sS[r * SSST + kcol]);
            a[1] = bitsf(sS[(r + 8) * SSST + kcol]);
            a[2] = bitsf(sS[r * SSST + kcol + 4]);
            a[3] = bitsf(sS[(r + 8) * SSST + kcol + 4]);
            #pragma unroll
            for (int nt = 0; nt < 2; nt++) {
                int d = wn * 16 + nt * 8 + (lane >> 2);
                bf[nt][0] = bitsf(sKV[(k0 + (lane & 3)) * SVST + d]);
                bf[nt][1] = bitsf(sKV[(k0 + 4 + (lane & 3)) * SVST + d]);
            }
            mma_tf32(yc[0], a, bf[0]);
            mma_tf32(yc[1], a, bf[1]);
        }
    }

    #pragma unroll
    for (int nt = 0; nt < 2; nt++) {
        int r = mt * 16 + (lane >> 2);
        int q = qb + r;
        int d = h * DD + wn * 16 + nt * 8 + (lane & 3) * 2;
        *(float2*)&Y[(size_t)(b * TT + q) * CC + d] =
            make_float2(yc[nt][0], yc[nt][1]);
        *(float2*)&Y[(size_t)(b * TT + q + 8) * CC + d] =
            make_float2(yc[nt][2], yc[nt][3]);
    }
}

// ---------------------------------------------------------------------------
// kernel_launch: fused QKV proj -> attention (+attn write) -> output proj
// Output layout: d_out = [ y (B*T*C) | attn (B*H*T*T) ]
// ---------------------------------------------------------------------------
extern "C" void kernel_launch(void* const* d_in, const int* in_sizes, int n_in,
                              void* d_out, int out_size)
{
    const float* x  = (const float*)d_in[0];
    const float* Wq = (const float*)d_in[1];
    const float* Wk = (const float*)d_in[2];
    const float* Wv = (const float*)d_in[3];
    const float* Wp = (const float*)d_in[4];

    float* out      = (float*)d_out;
    float* y_out    = out;
    float* attn_out = out + (size_t)BB * TT * CC;

    float *Qp, *Kp, *Vp, *Yp;
    cudaGetSymbolAddress((void**)&Qp, g_Q);
    cudaGetSymbolAddress((void**)&Kp, g_K);
    cudaGetSymbolAddress((void**)&Vp, g_V);
    cudaGetSymbolAddress((void**)&Yp, g_Y);

    const size_t gemm_smem = (size_t)(4 * 128 * GS) * sizeof(float);  // 73728
    cudaFuncSetAttribute(gemm_tf32_nt,
                         cudaFuncAttributeMaxDynamicSharedMemorySize,
                         (int)gemm_smem);

    // fused Q/K/V projections (z selects weight/output)
    dim3 gq(CC / 128, BT / 128, 3);
    gemm_tf32_nt<<<gq, 512, gemm_smem>>>(x, Wq, Wk, Wv, Qp, Kp, Vp, BT, CC, CC);

    const size_t attn_smem =
        (size_t)(32 * SSST + 32 * SQST + 64 * SVST) * sizeof(float);  // ~158.7KB
    cudaFuncSetAttribute(attn_kernel,
                         cudaFuncAttributeMaxDynamicSharedMemorySize,
                         (int)attn_smem);
    attn_kernel<<<dim3(TT / 32, HH, BB), 256, attn_smem>>>(Qp, Kp, Vp, attn_out, Yp);

    // output projection
    dim3 gp(CC / 128, BT / 128, 1);
    gemm_tf32_nt<<<gp, 512, gemm_smem>>>(Yp, Wp, Wp, Wp, y_out, y_out, y_out,
                                         BT, CC, CC);
}

// round 3
// speedup vs baseline: 3.7780x; 1.2939x over previous
#include <cuda_runtime.h>
#include <math.h>
#include <stdint.h>

#define BB   4
#define TT   1024
#define CC   1024
#define HH   16
#define DD   64
#define BT   (BB*TT)          // 4096

// Scratch (allocation-free rule: __device__ globals)
__device__ float g_Q[BT * CC];
__device__ float g_K[BT * CC];
__device__ float g_V[BT * CC];
__device__ float g_Y[BT * CC];
__device__ float g_X[BT * CC];       // tf32-rounded x
__device__ float g_W[4 * CC * CC];   // tf32-rounded Wq|Wk|Wv|Wp

// ---------------------------------------------------------------------------
// helpers
// ---------------------------------------------------------------------------
__device__ __forceinline__ float tf32r(float x) {
    uint32_t u;
    asm("cvt.rna.tf32.f32 %0, %1;" : "=r"(u) : "f"(x));
    return __uint_as_float(u);
}
__device__ __forceinline__ float4 tf32r4(float4 v) {
    float4 w;
    w.x = tf32r(v.x); w.y = tf32r(v.y); w.z = tf32r(v.z); w.w = tf32r(v.w);
    return w;
}
__device__ __forceinline__ uint32_t bitsf(float x) { return __float_as_uint(x); }

__device__ __forceinline__ void mma_tf32(float* c, const uint32_t* a, const uint32_t* b) {
    asm volatile(
        "mma.sync.aligned.m16n8k8.row.col.f32.tf32.tf32.f32 "
        "{%0,%1,%2,%3}, {%4,%5,%6,%7}, {%8,%9}, {%0,%1,%2,%3};"
        : "+f"(c[0]), "+f"(c[1]), "+f"(c[2]), "+f"(c[3])
        : "r"(a[0]), "r"(a[1]), "r"(a[2]), "r"(a[3]), "r"(b[0]), "r"(b[1]));
}

#define CPA16(dst_u32, src_ptr) \
    asm volatile("cp.async.cg.shared.global [%0], [%1], 16;" \
                 :: "r"(dst_u32), "l"(src_ptr))
#define CPCOMMIT() asm volatile("cp.async.commit_group;")
#define CPWAIT(n)  asm volatile("cp.async.wait_group %0;" :: "n"(n))

// ---------------------------------------------------------------------------
// prepass: tf32-round x -> g_X, weights -> g_W (concat)
// ---------------------------------------------------------------------------
__global__ void prepass(const float* __restrict__ x,
                        const float* __restrict__ wq, const float* __restrict__ wk,
                        const float* __restrict__ wv, const float* __restrict__ wp)
{
    int which = blockIdx.y;
    const float* src;
    float* dst;
    int n4;
    if (which == 0) { src = x;  dst = g_X; n4 = BT * CC / 4; }
    else {
        src = (which == 1) ? wq : (which == 2) ? wk : (which == 3) ? wv : wp;
        dst = g_W + (size_t)(which - 1) * CC * CC;
        n4 = CC * CC / 4;
    }
    for (int i = blockIdx.x * blockDim.x + threadIdx.x; i < n4;
         i += gridDim.x * blockDim.x) {
        float4 v = ((const float4*)src)[i];
        ((float4*)dst)[i] = tf32r4(v);
    }
}

// ---------------------------------------------------------------------------
// C[M,N] = A[M,K] @ W[N,K]^T, TF32 MMA, inputs pre-rounded.
// 128x128 tile, BK=32, 512 threads, 4-stage cp.async pipeline.
// blockIdx.z selects (W, C) pair (QKV fusion).  ro: round outputs to tf32.
// ---------------------------------------------------------------------------
#define GS 36
#define NT 32   // K/32 = 1024/32
__global__ __launch_bounds__(512, 1)
void gemm_tf32_nt(const float* __restrict__ A, const float* __restrict__ Wb,
                  float* __restrict__ C0, float* __restrict__ C1,
                  float* __restrict__ C2, int ro)
{
    const float* Bw = Wb + (size_t)blockIdx.z * CC * CC;
    float*       C  = (blockIdx.z == 0) ? C0 : (blockIdx.z == 1 ? C1 : C2);

    extern __shared__ float sm[];
    float* As = sm;                   // [4][128][GS]
    float* Bs = sm + 4 * 128 * GS;    // [4][128][GS]
    uint32_t sAu = (uint32_t)__cvta_generic_to_shared(As);
    uint32_t sBu = (uint32_t)__cvta_generic_to_shared(Bs);

    const int tid  = threadIdx.x;
    const int lane = tid & 31;
    const int warp = tid >> 5;            // 0..15
    const int wm   = (warp & 3) * 32;
    const int wn   = (warp >> 2) * 32;

    const float* Abase = A  + (size_t)(blockIdx.y * 128) * CC;
    const float* Bbase = Bw + (size_t)(blockIdx.x * 128) * CC;

    // stage loader: 2 granules A + 2 granules B per thread
    auto load_stage = [&](int kt, int s) {
        #pragma unroll
        for (int i = 0; i < 2; i++) {
            int g = tid + i * 512;             // 0..1023
            int row = g >> 3, c16 = g & 7;
            const float* srcA = Abase + (size_t)row * CC + kt * 32 + c16 * 4;
            const float* srcB = Bbase + (size_t)row * CC + kt * 32 + c16 * 4;
            CPA16(sAu + s * (128 * GS * 4) + row * (GS * 4) + c16 * 16, srcA);
            CPA16(sBu + s * (128 * GS * 4) + row * (GS * 4) + c16 * 16, srcB);
        }
        CPCOMMIT();
    };

    load_stage(0, 0);
    load_stage(1, 1);
    load_stage(2, 2);

    float acc[2][4][4];
    #pragma unroll
    for (int i = 0; i < 2; i++)
        #pragma unroll
        for (int j = 0; j < 4; j++)
            #pragma unroll
            for (int k = 0; k < 4; k++) acc[i][j][k] = 0.f;

    for (int kt = 0; kt < NT; kt++) {
        if (kt <= NT - 3)      { CPWAIT(2); }
        else if (kt == NT - 2) { CPWAIT(1); }
        else                   { CPWAIT(0); }
        __syncthreads();

        if (kt + 3 < NT) load_stage(kt + 3, (kt + 3) & 3);

        const float* Ab = As + (kt & 3) * (128 * GS);
        const float* Bb = Bs + (kt & 3) * (128 * GS);

        #pragma unroll
        for (int ks = 0; ks < 4; ks++) {
            const int k0 = ks * 8 + (lane & 3);
            uint32_t af[2][4], bf[4][2];
            #pragma unroll
            for (int mt = 0; mt < 2; mt++) {
                int r = wm + mt * 16 + (lane >> 2);
                af[mt][0] = bitsf(Ab[r * GS + k0]);
                af[mt][1] = bitsf(Ab[(r + 8) * GS + k0]);
                af[mt][2] = bitsf(Ab[r * GS + k0 + 4]);
                af[mt][3] = bitsf(Ab[(r + 8) * GS + k0 + 4]);
            }
            #pragma unroll
            for (int nt = 0; nt < 4; nt++) {
                int n = wn + nt * 8 + (lane >> 2);
                bf[nt][0] = bitsf(Bb[n * GS + k0]);
                bf[nt][1] = bitsf(Bb[n * GS + k0 + 4]);
            }
            #pragma unroll
            for (int mt = 0; mt < 2; mt++)
                #pragma unroll
                for (int nt = 0; nt < 4; nt++)
                    mma_tf32(acc[mt][nt], af[mt], bf[nt]);
        }
    }

    #pragma unroll
    for (int mt = 0; mt < 2; mt++) {
        int r0 = blockIdx.y * 128 + wm + mt * 16 + (lane >> 2);
        #pragma unroll
        for (int nt = 0; nt < 4; nt++) {
            int c0 = blockIdx.x * 128 + wn + nt * 8 + (lane & 3) * 2;
            float v0 = acc[mt][nt][0], v1 = acc[mt][nt][1];
            float v2 = acc[mt][nt][2], v3 = acc[mt][nt][3];
            if (ro) { v0 = tf32r(v0); v1 = tf32r(v1); v2 = tf32r(v2); v3 = tf32r(v3); }
            *(float2*)&C[(size_t)r0 * CC + c0]       = make_float2(v0, v1);
            *(float2*)&C[(size_t)(r0 + 8) * CC + c0] = make_float2(v2, v3);
        }
    }
}

// ---------------------------------------------------------------------------
// Attention: block = (b, h, 32 queries). 512 threads / 16 warps.
// QK^T and PV via TF32 MMA; K/V chunks (128 rows) double-buffered cp.async.
// Score strip sS[32][1028] fp32 in smem; K stride 68, V stride 72.
// ---------------------------------------------------------------------------
#define SSST 1028
#define SQST 68
#define KST  68
#define VST  72
#define KVBUF (128 * 72)      // floats per chunk buffer slot (max of both)
__global__ __launch_bounds__(512, 1)
void attn_kernel(const float* __restrict__ Q, const float* __restrict__ Km,
                 const float* __restrict__ V, float* __restrict__ attn,
                 float* __restrict__ Y)
{
    extern __shared__ float sm[];
    float* sS  = sm;                      // 32 * 1028
    float* sQ  = sS + 32 * SSST;          // 32 * 68
    float* sKV = sQ + 32 * SQST;          // 2 * KVBUF
    uint32_t sKVu = (uint32_t)__cvta_generic_to_shared(sKV);

    const int tid  = threadIdx.x;
    const int lane = tid & 31;
    const int warp = tid >> 5;            // 0..15
    const int qb   = blockIdx.x * 32;
    const int h    = blockIdx.y;
    const int b    = blockIdx.z;

    const float scale = 0.125f;
    const float slope = exp2f(-0.5f * (float)(h + 1));

    const int mt = warp & 1;              // 16-row group
    const int wn = warp >> 1;             // 0..7

    const float* Kb = Km + ((size_t)(b * TT)) * CC + h * DD;
    const float* Vb = V  + ((size_t)(b * TT)) * CC + h * DD;

    // K chunk loader: 128 rows x 64 floats, stride KST (byte stride 272)
    auto issueK = [&](int c, int buf) {
        const float* base = Kb + (size_t)(c * 128) * CC;
        #pragma unroll
        for (int i = 0; i < 4; i++) {
            int g = tid + i * 512;          // 0..2047
            int row = g >> 4, c16 = g & 15;
            CPA16(sKVu + buf * (KVBUF * 4) + row * (KST * 4) + c16 * 16,
                  base + (size_t)row * CC + c16 * 4);
        }
        CPCOMMIT();
    };
    auto issueV = [&](int c, int buf) {
        const float* base = Vb + (size_t)(c * 128) * CC;
        #pragma unroll
        for (int i = 0; i < 4; i++) {
            int g = tid + i * 512;
            int row = g >> 4, c16 = g & 15;
            CPA16(sKVu + buf * (KVBUF * 4) + row * (VST * 4) + c16 * 16,
                  base + (size_t)row * CC + c16 * 4);
        }
        CPCOMMIT();
    };

    // ---- Q tile [32 x 64] -> sQ (already tf32-rounded in gmem) ----
    {
        const float* Qb = Q + ((size_t)(b * TT + qb)) * CC + h * DD;
        int r = tid >> 4, c4 = (tid & 15) << 2;
        *(float4*)(sQ + r * SQST + c4) = *(const float4*)(Qb + (size_t)r * CC + c4);
    }

    // ---- scores: 8 chunks of 128 cols, double buffered ----
    issueK(0, 0);
    int buf = 0;
    for (int c = 0; c < 8; c++) {
        if (c + 1 < 8) issueK(c + 1, buf ^ 1);
        if (c < 7) { CPWAIT(1); } else { CPWAIT(0); }
        __syncthreads();

        const float* sK = sKV + buf * KVBUF;
        float cr[2][4];
        #pragma unroll
        for (int nt = 0; nt < 2; nt++)
            #pragma unroll
            for (int i = 0; i < 4; i++) cr[nt][i] = 0.f;

        #pragma unroll
        for (int ks = 0; ks < 8; ks++) {
            const int k0 = ks * 8 + (lane & 3);
            uint32_t a[4], bf2[2][2];
            int r = mt * 16 + (lane >> 2);
            a[0] = bitsf(sQ[r * SQST + k0]);
            a[1] = bitsf(sQ[(r + 8) * SQST + k0]);
            a[2] = bitsf(sQ[r * SQST + k0 + 4]);
            a[3] = bitsf(sQ[(r + 8) * SQST + k0 + 4]);
            #pragma unroll
            for (int nt = 0; nt < 2; nt++) {
                int n = wn * 16 + nt * 8 + (lane >> 2);
                bf2[nt][0] = bitsf(sK[n * KST + k0]);
                bf2[nt][1] = bitsf(sK[n * KST + k0 + 4]);
            }
            mma_tf32(cr[0], a, bf2[0]);
            mma_tf32(cr[1], a, bf2[1]);
        }

        const int kc = c * 128;
        #pragma unroll
        for (int nt = 0; nt < 2; nt++) {
            int r0  = mt * 16 + (lane >> 2);
            int cl  = wn * 16 + nt * 8 + (lane & 3) * 2;
            float q0 = (float)(qb + r0), q8 = q0 + 8.0f;
            float k0f = (float)(kc + cl), k1f = k0f + 1.0f;
            *(float2*)&sS[r0 * SSST + kc + cl] = make_float2(
                cr[nt][0] * scale - slope * fabsf(q0 - k0f),
                cr[nt][1] * scale - slope * fabsf(q0 - k1f));
            *(float2*)&sS[(r0 + 8) * SSST + kc + cl] = make_float2(
                cr[nt][2] * scale - slope * fabsf(q8 - k0f),
                cr[nt][3] * scale - slope * fabsf(q8 - k1f));
        }
        __syncthreads();
        buf ^= 1;
    }

    // prefetch V chunk 0 while softmax runs
    issueV(0, 0);

    // ---- softmax: each warp owns 2 rows; write attn fp32, strip -> tf32 P ----
    const size_t attn_base = (((size_t)(b * HH + h)) * TT + qb) * TT;
    #pragma unroll
    for (int rr = 0; rr < 2; rr++) {
        int q = warp * 2 + rr;
        float* row = sS + q * SSST;
        float m = -1e30f;
        #pragma unroll 8
        for (int it = 0; it < 32; it++) m = fmaxf(m, row[it * 32 + lane]);
        #pragma unroll
        for (int off = 16; off; off >>= 1) m = fmaxf(m, __shfl_xor_sync(~0u, m, off));
        float s = 0.f;
        #pragma unroll 8
        for (int it = 0; it < 32; it++) {
            float e = __expf(row[it * 32 + lane] - m);
            row[it * 32 + lane] = e;
            s += e;
        }
        #pragma unroll
        for (int off = 16; off; off >>= 1) s += __shfl_xor_sync(~0u, s, off);
        float inv = 1.0f / s;
        float* out = attn + attn_base + (size_t)q * TT;
        #pragma unroll
        for (int it = 0; it < 8; it++) {
            int cx = it * 128 + lane * 4;
            float4 v = *(float4*)(row + cx);
            v.x *= inv; v.y *= inv; v.z *= inv; v.w *= inv;
            *(float4*)(out + cx) = v;          // fp32 attn
            *(float4*)(row + cx) = tf32r4(v);  // tf32 P
        }
    }

    // ---- PV: out[32][64], warp tile 16x8 (mt x wn), 8 chunks dbl-buffered ----
    float yc[4] = {0.f, 0.f, 0.f, 0.f};
    const int dcol = wn * 8 + (lane >> 2);

    buf = 0;
    for (int c = 0; c < 8; c++) {
        if (c + 1 < 8) issueV(c + 1, buf ^ 1);
        if (c < 7) { CPWAIT(1); } else { CPWAIT(0); }
        __syncthreads();   // also publishes softmax P on first iteration

        const float* sV = sKV + buf * KVBUF;
        const int kc = c * 128;
        #pragma unroll
        for (int kk = 0; kk < 16; kk++) {
            const int k0 = kk * 8;
            uint32_t a[4], b2[2];
            int r = mt * 16 + (lane >> 2);
            int kcol = kc + k0 + (lane & 3);
            a[0] = bitsf(sS[r * SSST + kcol]);
            a[1] = bitsf(sS[(r + 8) * SSST + kcol]);
            a[2] = bitsf(sS[r * SSST + kcol + 4]);
            a[3] = bitsf(sS[(r + 8) * SSST + kcol + 4]);
            b2[0] = bitsf(sV[(k0 + (lane & 3)) * VST + dcol]);
            b2[1] = bitsf(sV[(k0 + 4 + (lane & 3)) * VST + dcol]);
            mma_tf32(yc, a, b2);
        }
        __syncthreads();
        buf ^= 1;
    }

    // Y store (tf32-rounded: it feeds the output projection)
    {
        int r = mt * 16 + (lane >> 2);
        int q = qb + r;
        int d = h * DD + wn * 8 + (lane & 3) * 2;
        *(float2*)&Y[(size_t)(b * TT + q) * CC + d] =
            make_float2(tf32r(yc[0]), tf32r(yc[1]));
        *(float2*)&Y[(size_t)(b * TT + q + 8) * CC + d] =
            make_float2(tf32r(yc[2]), tf32r(yc[3]));
    }
}

// ---------------------------------------------------------------------------
// launch: prepass -> QKV proj -> attention -> output proj
// d_out = [ y (B*T*C) | attn (B*H*T*T) ]
// ---------------------------------------------------------------------------
extern "C" void kernel_launch(void* const* d_in, const int* in_sizes, int n_in,
                              void* d_out, int out_size)
{
    const float* x  = (const float*)d_in[0];
    const float* Wq = (const float*)d_in[1];
    const float* Wk = (const float*)d_in[2];
    const float* Wv = (const float*)d_in[3];
    const float* Wp = (const float*)d_in[4];

    float* out      = (float*)d_out;
    float* y_out    = out;
    float* attn_out = out + (size_t)BB * TT * CC;

    float *Qp, *Kp, *Vp, *Yp, *Xp, *Wc;
    cudaGetSymbolAddress((void**)&Qp, g_Q);
    cudaGetSymbolAddress((void**)&Kp, g_K);
    cudaGetSymbolAddress((void**)&Vp, g_V);
    cudaGetSymbolAddress((void**)&Yp, g_Y);
    cudaGetSymbolAddress((void**)&Xp, g_X);
    cudaGetSymbolAddress((void**)&Wc, g_W);

    prepass<<<dim3(1024, 5), 256>>>(x, Wq, Wk, Wv, Wp);

    const size_t gemm_smem = (size_t)(8 * 128 * GS) * sizeof(float);  // 147456
    cudaFuncSetAttribute(gemm_tf32_nt,
                         cudaFuncAttributeMaxDynamicSharedMemorySize,
                         (int)gemm_smem);

    dim3 gq(CC / 128, BT / 128, 3);
    gemm_tf32_nt<<<gq, 512, gemm_smem>>>(Xp, Wc, Qp, Kp, Vp, 1);

    const size_t attn_smem =
        (size_t)(32 * SSST + 32 * SQST + 2 * KVBUF) * sizeof(float);  // 214016
    cudaFuncSetAttribute(attn_kernel,
                         cudaFuncAttributeMaxDynamicSharedMemorySize,
                         (int)attn_smem);
    attn_kernel<<<dim3(TT / 32, HH, BB), 512, attn_smem>>>(Qp, Kp, Vp, attn_out, Yp);

    dim3 gp(CC / 128, BT / 128, 1);
    gemm_tf32_nt<<<gp, 512, gemm_smem>>>(Yp, Wc + (size_t)3 * CC * CC,
                                         y_out, y_out, y_out, 0);
}

// round 5
// speedup vs baseline: 4.3058x; 1.1397x over previous
#include <cuda_runtime.h>
#include <math.h>
#include <stdint.h>

#define BB   4
#define TT   1024
#define CC   1024
#define HH   16
#define DD   64
#define BT   (BB*TT)          // 4096

// Scratch (allocation-free rule: __device__ globals)
__device__ float g_Q[BT * CC];
__device__ float g_K[BT * CC];
__device__ float g_V[BT * CC];
__device__ float g_Y[BT * CC];
__device__ float g_X[BT * CC];       // tf32-rounded x
__device__ float g_W[4 * CC * CC];   // tf32-rounded Wq|Wk|Wv|Wp

// ---------------------------------------------------------------------------
// helpers
// ---------------------------------------------------------------------------
__device__ __forceinline__ float tf32r(float x) {
    uint32_t u;
    asm("cvt.rna.tf32.f32 %0, %1;" : "=r"(u) : "f"(x));
    return __uint_as_float(u);
}
__device__ __forceinline__ float4 tf32r4(float4 v) {
    float4 w;
    w.x = tf32r(v.x); w.y = tf32r(v.y); w.z = tf32r(v.z); w.w = tf32r(v.w);
    return w;
}
__device__ __forceinline__ uint32_t bitsf(float x) { return __float_as_uint(x); }
__device__ __forceinline__ uint32_t tf32b(float x) {
    uint32_t u;
    asm("cvt.rna.tf32.f32 %0, %1;" : "=r"(u) : "f"(x));
    return u;
}

__device__ __forceinline__ void mma_tf32(float* c, const uint32_t* a, const uint32_t* b) {
    asm volatile(
        "mma.sync.aligned.m16n8k8.row.col.f32.tf32.tf32.f32 "
        "{%0,%1,%2,%3}, {%4,%5,%6,%7}, {%8,%9}, {%0,%1,%2,%3};"
        : "+f"(c[0]), "+f"(c[1]), "+f"(c[2]), "+f"(c[3])
        : "r"(a[0]), "r"(a[1]), "r"(a[2]), "r"(a[3]), "r"(b[0]), "r"(b[1]));
}

#define CPA16(dst_u32, src_ptr) \
    asm volatile("cp.async.cg.shared.global [%0], [%1], 16;" \
                 :: "r"(dst_u32), "l"(src_ptr))
#define CPCOMMIT() asm volatile("cp.async.commit_group;")
#define CPWAIT(n)  asm volatile("cp.async.wait_group %0;" :: "n"(n))

// ---------------------------------------------------------------------------
// prepass: tf32-round x -> g_X, weights -> g_W (concat)
// ---------------------------------------------------------------------------
__global__ void prepass(const float* __restrict__ x,
                        const float* __restrict__ wq, const float* __restrict__ wk,
                        const float* __restrict__ wv, const float* __restrict__ wp)
{
    int which = blockIdx.y;
    const float* src;
    float* dst;
    int n4;
    if (which == 0) { src = x;  dst = g_X; n4 = BT * CC / 4; }
    else {
        src = (which == 1) ? wq : (which == 2) ? wk : (which == 3) ? wv : wp;
        dst = g_W + (size_t)(which - 1) * CC * CC;
        n4 = CC * CC / 4;
    }
    for (int i = blockIdx.x * blockDim.x + threadIdx.x; i < n4;
         i += gridDim.x * blockDim.x) {
        float4 v = ((const float4*)src)[i];
        ((float4*)dst)[i] = tf32r4(v);
    }
}

// ---------------------------------------------------------------------------
// C[M,N] = A[M,K] @ W[N,K]^T, TF32 MMA, inputs pre-rounded.
// 128x128 tile, BK=32, 512 threads, 4-stage cp.async pipeline.
// ---------------------------------------------------------------------------
#define GS 36
#define NTG 32   // K/32
__global__ __launch_bounds__(512, 1)
void gemm_tf32_nt(const float* __restrict__ A, const float* __restrict__ Wb,
                  float* __restrict__ C0, float* __restrict__ C1,
                  float* __restrict__ C2, int ro)
{
    const float* Bw = Wb + (size_t)blockIdx.z * CC * CC;
    float*       C  = (blockIdx.z == 0) ? C0 : (blockIdx.z == 1 ? C1 : C2);

    extern __shared__ float sm[];
    float* As = sm;                   // [4][128][GS]
    float* Bs = sm + 4 * 128 * GS;    // [4][128][GS]
    uint32_t sAu = (uint32_t)__cvta_generic_to_shared(As);
    uint32_t sBu = (uint32_t)__cvta_generic_to_shared(Bs);

    const int tid  = threadIdx.x;
    const int lane = tid & 31;
    const int warp = tid >> 5;
    const int wm   = (warp & 3) * 32;
    const int wn   = (warp >> 2) * 32;

    const float* Abase = A  + (size_t)(blockIdx.y * 128) * CC;
    const float* Bbase = Bw + (size_t)(blockIdx.x * 128) * CC;

    auto load_stage = [&](int kt, int s) {
        #pragma unroll
        for (int i = 0; i < 2; i++) {
            int g = tid + i * 512;
            int row = g >> 3, c16 = g & 7;
            const float* srcA = Abase + (size_t)row * CC + kt * 32 + c16 * 4;
            const float* srcB = Bbase + (size_t)row * CC + kt * 32 + c16 * 4;
            CPA16(sAu + s * (128 * GS * 4) + row * (GS * 4) + c16 * 16, srcA);
            CPA16(sBu + s * (128 * GS * 4) + row * (GS * 4) + c16 * 16, srcB);
        }
        CPCOMMIT();
    };

    load_stage(0, 0);
    load_stage(1, 1);
    load_stage(2, 2);

    float acc[2][4][4];
    #pragma unroll
    for (int i = 0; i < 2; i++)
        #pragma unroll
        for (int j = 0; j < 4; j++)
            #pragma unroll
            for (int k = 0; k < 4; k++) acc[i][j][k] = 0.f;

    for (int kt = 0; kt < NTG; kt++) {
        if (kt <= NTG - 3)      { CPWAIT(2); }
        else if (kt == NTG - 2) { CPWAIT(1); }
        else                    { CPWAIT(0); }
        __syncthreads();

        if (kt + 3 < NTG) load_stage(kt + 3, (kt + 3) & 3);

        const float* Ab = As + (kt & 3) * (128 * GS);
        const float* Bb = Bs + (kt & 3) * (128 * GS);

        #pragma unroll
        for (int ks = 0; ks < 4; ks++) {
            const int k0 = ks * 8 + (lane & 3);
            uint32_t af[2][4], bf[4][2];
            #pragma unroll
            for (int mt = 0; mt < 2; mt++) {
                int r = wm + mt * 16 + (lane >> 2);
                af[mt][0] = bitsf(Ab[r * GS + k0]);
                af[mt][1] = bitsf(Ab[(r + 8) * GS + k0]);
                af[mt][2] = bitsf(Ab[r * GS + k0 + 4]);
                af[mt][3] = bitsf(Ab[(r + 8) * GS + k0 + 4]);
            }
            #pragma unroll
            for (int nt = 0; nt < 4; nt++) {
                int n = wn + nt * 8 + (lane >> 2);
                bf[nt][0] = bitsf(Bb[n * GS + k0]);
                bf[nt][1] = bitsf(Bb[n * GS + k0 + 4]);
            }
            #pragma unroll
            for (int mt = 0; mt < 2; mt++)
                #pragma unroll
                for (int nt = 0; nt < 4; nt++)
                    mma_tf32(acc[mt][nt], af[mt], bf[nt]);
        }
    }

    #pragma unroll
    for (int mt = 0; mt < 2; mt++) {
        int r0 = blockIdx.y * 128 + wm + mt * 16 + (lane >> 2);
        #pragma unroll
        for (int nt = 0; nt < 4; nt++) {
            int c0 = blockIdx.x * 128 + wn + nt * 8 + (lane & 3) * 2;
            float v0 = acc[mt][nt][0], v1 = acc[mt][nt][1];
            float v2 = acc[mt][nt][2], v3 = acc[mt][nt][3];
            if (ro) { v0 = tf32r(v0); v1 = tf32r(v1); v2 = tf32r(v2); v3 = tf32r(v3); }
            *(float2*)&C[(size_t)r0 * CC + c0]       = make_float2(v0, v1);
            *(float2*)&C[(size_t)(r0 + 8) * CC + c0] = make_float2(v2, v3);
        }
    }
}

// ---------------------------------------------------------------------------
// Kernel A: scores + ALiBi + softmax + attn write. block=(b,h,32q), 512 thr.
// Q fragments preloaded to registers (loop-invariant). No PV here.
// ---------------------------------------------------------------------------
#define SSST 1028
#define SQST 68
#define KST  68
#define KBUF (128 * KST)
__global__ __launch_bounds__(512, 1)
void attn_score_kernel(const float* __restrict__ Q, const float* __restrict__ Km,
                       float* __restrict__ attn)
{
    extern __shared__ float sm[];
    float* sS = sm;                      // 32 * 1028
    float* sQ = sS + 32 * SSST;          // 32 * 68
    float* sK = sQ + 32 * SQST;          // 2 * KBUF
    uint32_t sKu = (uint32_t)__cvta_generic_to_shared(sK);

    const int tid  = threadIdx.x;
    const int lane = tid & 31;
    const int warp = tid >> 5;           // 0..15
    const int qb   = blockIdx.x * 32;
    const int h    = blockIdx.y;
    const int b    = blockIdx.z;

    const float scale = 0.125f;
    const float slope = exp2f(-0.5f * (float)(h + 1));

    const int mt = warp & 1;
    const int wn = warp >> 1;

    const float* Kb = Km + ((size_t)(b * TT)) * CC + h * DD;

    auto issueK = [&](int c, int buf) {
        const float* base = Kb + (size_t)(c * 128) * CC;
        #pragma unroll
        for (int i = 0; i < 4; i++) {
            int g = tid + i * 512;
            int row = g >> 4, c16 = g & 15;
            CPA16(sKu + buf * (KBUF * 4) + row * (KST * 4) + c16 * 16,
                  base + (size_t)row * CC + c16 * 4);
        }
        CPCOMMIT();
    };

    issueK(0, 0);

    // Q tile [32 x 64] -> sQ
    {
        const float* Qb = Q + ((size_t)(b * TT + qb)) * CC + h * DD;
        int r = tid >> 4, c4 = (tid & 15) << 2;
        *(float4*)(sQ + r * SQST + c4) = *(const float4*)(Qb + (size_t)r * CC + c4);
    }
    __syncthreads();

    // preload Q fragments for all 8 k-steps (loop-invariant across chunks)
    uint32_t aq[8][4];
    {
        int rq = mt * 16 + (lane >> 2);
        #pragma unroll
        for (int ks = 0; ks < 8; ks++) {
            int k0 = ks * 8 + (lane & 3);
            aq[ks][0] = bitsf(sQ[rq * SQST + k0]);
            aq[ks][1] = bitsf(sQ[(rq + 8) * SQST + k0]);
            aq[ks][2] = bitsf(sQ[rq * SQST + k0 + 4]);
            aq[ks][3] = bitsf(sQ[(rq + 8) * SQST + k0 + 4]);
        }
    }

    int buf = 0;
    for (int c = 0; c < 8; c++) {
        if (c + 1 < 8) issueK(c + 1, buf ^ 1);
        if (c < 7) { CPWAIT(1); } else { CPWAIT(0); }
        __syncthreads();

        const float* K = sK + buf * KBUF;
        float cr[2][4];
        #pragma unroll
        for (int nt = 0; nt < 2; nt++)
            #pragma unroll
            for (int i = 0; i < 4; i++) cr[nt][i] = 0.f;

        #pragma unroll
        for (int ks = 0; ks < 8; ks++) {
            const int k0 = ks * 8 + (lane & 3);
            uint32_t bf2[2][2];
            #pragma unroll
            for (int nt = 0; nt < 2; nt++) {
                int n = wn * 16 + nt * 8 + (lane >> 2);
                bf2[nt][0] = bitsf(K[n * KST + k0]);
                bf2[nt][1] = bitsf(K[n * KST + k0 + 4]);
            }
            mma_tf32(cr[0], aq[ks], bf2[0]);
            mma_tf32(cr[1], aq[ks], bf2[1]);
        }

        const int kc = c * 128;
        #pragma unroll
        for (int nt = 0; nt < 2; nt++) {
            int r0 = mt * 16 + (lane >> 2);
            int cl = wn * 16 + nt * 8 + (lane & 3) * 2;
            float q0 = (float)(qb + r0), q8 = q0 + 8.0f;
            float k0f = (float)(kc + cl), k1f = k0f + 1.0f;
            *(float2*)&sS[r0 * SSST + kc + cl] = make_float2(
                cr[nt][0] * scale - slope * fabsf(q0 - k0f),
                cr[nt][1] * scale - slope * fabsf(q0 - k1f));
            *(float2*)&sS[(r0 + 8) * SSST + kc + cl] = make_float2(
                cr[nt][2] * scale - slope * fabsf(q8 - k0f),
                cr[nt][3] * scale - slope * fabsf(q8 - k1f));
        }
        __syncthreads();
        buf ^= 1;
    }
    // (last loop iteration ended with __syncthreads -> sS fully published)

    // softmax: each warp owns 2 rows; exp values kept in registers
    const size_t attn_base = (((size_t)(b * HH + h)) * TT + qb) * TT;
    #pragma unroll
    for (int rr = 0; rr < 2; rr++) {
        int q = warp * 2 + rr;
        float* row = sS + q * SSST;
        float4 e[8];
        float m = -1e30f;
        #pragma unroll
        for (int it = 0; it < 8; it++) {
            e[it] = *(float4*)(row + it * 128 + lane * 4);
            m = fmaxf(m, fmaxf(fmaxf(e[it].x, e[it].y), fmaxf(e[it].z, e[it].w)));
        }
        #pragma unroll
        for (int off = 16; off; off >>= 1) m = fmaxf(m, __shfl_xor_sync(~0u, m, off));
        float s = 0.f;
        #pragma unroll
        for (int it = 0; it < 8; it++) {
            e[it].x = __expf(e[it].x - m);
            e[it].y = __expf(e[it].y - m);
            e[it].z = __expf(e[it].z - m);
            e[it].w = __expf(e[it].w - m);
            s += (e[it].x + e[it].y) + (e[it].z + e[it].w);
        }
        #pragma unroll
        for (int off = 16; off; off >>= 1) s += __shfl_xor_sync(~0u, s, off);
        float inv = 1.0f / s;
        float* out = attn + attn_base + (size_t)q * TT;
        #pragma unroll
        for (int it = 0; it < 8; it++) {
            float4 v = e[it];
            v.x *= inv; v.y *= inv; v.z *= inv; v.w *= inv;
            *(float4*)(out + it * 128 + lane * 4) = v;
        }
    }
}

// ---------------------------------------------------------------------------
// Kernel B: Y[128x64] = P[128x1024] @ V[1024x64] per (b,h,qtile).
// P read fp32 from attn output, tf32-rounded in registers.
// 256 thr, 4-stage cp.async pipeline (prefetch kt+3 -> buffer (kt-1)&3: safe).
// ---------------------------------------------------------------------------
#define PST 36
#define VST 72
#define BSTAGE_F (128 * PST + 32 * VST)   // floats per stage
__global__ __launch_bounds__(256, 2)
void pv_kernel(const float* __restrict__ attn, const float* __restrict__ V,
               float* __restrict__ Y)
{
    extern __shared__ float sm[];
    float* Ps = sm;                                // [4][128][PST]
    float* Vs = sm + 4 * 128 * PST;                // [4][32][VST]
    uint32_t sPu = (uint32_t)__cvta_generic_to_shared(Ps);
    uint32_t sVu = (uint32_t)__cvta_generic_to_shared(Vs);

    const int tid  = threadIdx.x;
    const int lane = tid & 31;
    const int warp = tid >> 5;            // 0..7
    const int qb   = blockIdx.x * 128;
    const int h    = blockIdx.y;
    const int b    = blockIdx.z;

    const int wm = (warp >> 1) * 32;      // 4 row groups of 32
    const int wn = (warp & 1) * 32;       // 2 col groups of 32

    const float* Pb = attn + (((size_t)(b * HH + h)) * TT + qb) * TT;
    const float* Vb = V + ((size_t)(b * TT)) * CC + h * DD;

    auto load_stage = [&](int kt, int s) {
        // P: 128 rows x 32 k-floats (1024 granules, 4/thread)
        #pragma unroll
        for (int i = 0; i < 4; i++) {
            int g = tid + i * 256;
            int row = g >> 3, c16 = g & 7;
            CPA16(sPu + s * (128 * PST * 4) + row * (PST * 4) + c16 * 16,
                  Pb + (size_t)row * TT + kt * 32 + c16 * 4);
        }
        // V: 32 rows x 64 floats (512 granules, 2/thread)
        #pragma unroll
        for (int i = 0; i < 2; i++) {
            int g = tid + i * 256;
            int row = g >> 4, c16 = g & 15;
            CPA16(sVu + s * (32 * VST * 4) + row * (VST * 4) + c16 * 16,
                  Vb + (size_t)(kt * 32 + row) * CC + c16 * 4);
        }
        CPCOMMIT();
    };

    load_stage(0, 0);
    load_stage(1, 1);
    load_stage(2, 2);

    float acc[2][4][4];
    #pragma unroll
    for (int i = 0; i < 2; i++)
        #pragma unroll
        for (int j = 0; j < 4; j++)
            #pragma unroll
            for (int k = 0; k < 4; k++) acc[i][j][k] = 0.f;

    const int NT2 = 32;
    for (int kt = 0; kt < NT2; kt++) {
        if (kt <= NT2 - 3)      { CPWAIT(2); }
        else if (kt == NT2 - 2) { CPWAIT(1); }
        else                    { CPWAIT(0); }
        __syncthreads();

        if (kt + 3 < NT2) load_stage(kt + 3, (kt + 3) & 3);

        const float* Pt = Ps + (kt & 3) * (128 * PST);
        const float* Vt = Vs + (kt & 3) * (32 * VST);

        #pragma unroll
        for (int ks = 0; ks < 4; ks++) {
            const int k0 = ks * 8 + (lane & 3);
            const int k0v = ks * 8;
            uint32_t af[2][4], bf[4][2];
            #pragma unroll
            for (int mt2 = 0; mt2 < 2; mt2++) {
                int r = wm + mt2 * 16 + (lane >> 2);
                af[mt2][0] = tf32b(Pt[r * PST + k0]);
                af[mt2][1] = tf32b(Pt[(r + 8) * PST + k0]);
                af[mt2][2] = tf32b(Pt[r * PST + k0 + 4]);
                af[mt2][3] = tf32b(Pt[(r + 8) * PST + k0 + 4]);
            }
            #pragma unroll
            for (int nt = 0; nt < 4; nt++) {
                int n = wn + nt * 8 + (lane >> 2);
                bf[nt][0] = bitsf(Vt[(k0v + (lane & 3)) * VST + n]);
                bf[nt][1] = bitsf(Vt[(k0v + 4 + (lane & 3)) * VST + n]);
            }
            #pragma unroll
            for (int mt2 = 0; mt2 < 2; mt2++)
                #pragma unroll
                for (int nt = 0; nt < 4; nt++)
                    mma_tf32(acc[mt2][nt], af[mt2], bf[nt]);
        }
    }

    // Y store (tf32-rounded: feeds the output projection)
    #pragma unroll
    for (int mt2 = 0; mt2 < 2; mt2++) {
        int r0 = qb + wm + mt2 * 16 + (lane >> 2);
        #pragma unroll
        for (int nt = 0; nt < 4; nt++) {
            int c0 = wn + nt * 8 + (lane & 3) * 2;
            float* y0 = &Y[(size_t)(b * TT + r0) * CC + h * DD + c0];
            float* y1 = &Y[(size_t)(b * TT + r0 + 8) * CC + h * DD + c0];
            *(float2*)y0 = make_float2(tf32r(acc[mt2][nt][0]), tf32r(acc[mt2][nt][1]));
            *(float2*)y1 = make_float2(tf32r(acc[mt2][nt][2]), tf32r(acc[mt2][nt][3]));
        }
    }
}

// ---------------------------------------------------------------------------
// launch: prepass -> QKV proj -> scores/softmax -> PV -> output proj
// d_out = [ y (B*T*C) | attn (B*H*T*T) ]
// ---------------------------------------------------------------------------
extern "C" void kernel_launch(void* const* d_in, const int* in_sizes, int n_in,
                              void* d_out, int out_size)
{
    const float* x  = (const float*)d_in[0];
    const float* Wq = (const float*)d_in[1];
    const float* Wk = (const float*)d_in[2];
    const float* Wv = (const float*)d_in[3];
    const float* Wp = (const float*)d_in[4];

    float* out      = (float*)d_out;
    float* y_out    = out;
    float* attn_out = out + (size_t)BB * TT * CC;

    float *Qp, *Kp, *Vp, *Yp, *Xp, *Wc;
    cudaGetSymbolAddress((void**)&Qp, g_Q);
    cudaGetSymbolAddress((void**)&Kp, g_K);
    cudaGetSymbolAddress((void**)&Vp, g_V);
    cudaGetSymbolAddress((void**)&Yp, g_Y);
    cudaGetSymbolAddress((void**)&Xp, g_X);
    cudaGetSymbolAddress((void**)&Wc, g_W);

    prepass<<<dim3(1024, 5), 256>>>(x, Wq, Wk, Wv, Wp);

    const size_t gemm_smem = (size_t)(8 * 128 * GS) * sizeof(float);  // 147456
    cudaFuncSetAttribute(gemm_tf32_nt,
                         cudaFuncAttributeMaxDynamicSharedMemorySize,
                         (int)gemm_smem);

    dim3 gq(CC / 128, BT / 128, 3);
    gemm_tf32_nt<<<gq, 512, gemm_smem>>>(Xp, Wc, Qp, Kp, Vp, 1);

    const size_t scoreA_smem =
        (size_t)(32 * SSST + 32 * SQST + 2 * KBUF) * sizeof(float);   // 209920
    cudaFuncSetAttribute(attn_score_kernel,
                         cudaFuncAttributeMaxDynamicSharedMemorySize,
                         (int)scoreA_smem);
    attn_score_kernel<<<dim3(TT / 32, HH, BB), 512, scoreA_smem>>>(Qp, Kp, attn_out);

    const size_t pv_smem = (size_t)(4 * BSTAGE_F) * sizeof(float);    // 110592
    cudaFuncSetAttribute(pv_kernel,
                         cudaFuncAttributeMaxDynamicSharedMemorySize,
                         (int)pv_smem);
    pv_kernel<<<dim3(TT / 128, HH, BB), 256, pv_smem>>>(attn_out, Vp, Yp);

    dim3 gp(CC / 128, BT / 128, 1);
    gemm_tf32_nt<<<gp, 512, gemm_smem>>>(Yp, Wc + (size_t)3 * CC * CC,
                                         y_out, y_out, y_out, 0);
}

// round 6
// speedup vs baseline: 4.5309x; 1.0523x over previous
#include <cuda_runtime.h>
#include <math.h>
#include <stdint.h>

#define BB   4
#define TT   1024
#define CC   1024
#define HH   16
#define DD   64
#define BT   (BB*TT)          // 4096

// Scratch (allocation-free rule: __device__ globals)
__device__ float g_Q[BT * CC];
__device__ float g_K[BT * CC];
__device__ float g_V[BT * CC];
__device__ float g_Y[BT * CC];
__device__ float g_X[BT * CC];       // tf32-rounded x
__device__ float g_W[4 * CC * CC];   // tf32-rounded Wq|Wk|Wv|Wp

// ---------------------------------------------------------------------------
// helpers
// ---------------------------------------------------------------------------
__device__ __forceinline__ float tf32r(float x) {
    uint32_t u;
    asm("cvt.rna.tf32.f32 %0, %1;" : "=r"(u) : "f"(x));
    return __uint_as_float(u);
}
__device__ __forceinline__ float4 tf32r4(float4 v) {
    float4 w;
    w.x = tf32r(v.x); w.y = tf32r(v.y); w.z = tf32r(v.z); w.w = tf32r(v.w);
    return w;
}
__device__ __forceinline__ uint32_t bitsf(float x) { return __float_as_uint(x); }
__device__ __forceinline__ uint32_t tf32b(float x) {
    uint32_t u;
    asm("cvt.rna.tf32.f32 %0, %1;" : "=r"(u) : "f"(x));
    return u;
}

__device__ __forceinline__ void mma_tf32(float* c, const uint32_t* a, const uint32_t* b) {
    asm volatile(
        "mma.sync.aligned.m16n8k8.row.col.f32.tf32.tf32.f32 "
        "{%0,%1,%2,%3}, {%4,%5,%6,%7}, {%8,%9}, {%0,%1,%2,%3};"
        : "+f"(c[0]), "+f"(c[1]), "+f"(c[2]), "+f"(c[3])
        : "r"(a[0]), "r"(a[1]), "r"(a[2]), "r"(a[3]), "r"(b[0]), "r"(b[1]));
}

// ldmatrix x4: loads four 8x8 b16 matrices == one tf32 m16k8 (or n16k8) fragment
__device__ __forceinline__ void ldsm_x4(uint32_t& r0, uint32_t& r1,
                                        uint32_t& r2, uint32_t& r3, uint32_t addr) {
    asm volatile("ldmatrix.sync.aligned.m8n8.x4.shared.b16 {%0,%1,%2,%3}, [%4];"
                 : "=r"(r0), "=r"(r1), "=r"(r2), "=r"(r3) : "r"(addr));
}

#define CPA16(dst_u32, src_ptr) \
    asm volatile("cp.async.cg.shared.global [%0], [%1], 16;" \
                 :: "r"(dst_u32), "l"(src_ptr))
#define CPCOMMIT() asm volatile("cp.async.commit_group;")
#define CPWAIT(n)  asm volatile("cp.async.wait_group %0;" :: "n"(n))

// ---------------------------------------------------------------------------
// prepass: tf32-round x -> g_X, weights -> g_W (concat)
// ---------------------------------------------------------------------------
__global__ void prepass(const float* __restrict__ x,
                        const float* __restrict__ wq, const float* __restrict__ wk,
                        const float* __restrict__ wv, const float* __restrict__ wp)
{
    int which = blockIdx.y;
    const float* src;
    float* dst;
    int n4;
    if (which == 0) { src = x;  dst = g_X; n4 = BT * CC / 4; }
    else {
        src = (which == 1) ? wq : (which == 2) ? wk : (which == 3) ? wv : wp;
        dst = g_W + (size_t)(which - 1) * CC * CC;
        n4 = CC * CC / 4;
    }
    for (int i = blockIdx.x * blockDim.x + threadIdx.x; i < n4;
         i += gridDim.x * blockDim.x) {
        float4 v = ((const float4*)src)[i];
        ((float4*)dst)[i] = tf32r4(v);
    }
}

// ---------------------------------------------------------------------------
// C[M,N] = A[M,K] @ W[N,K]^T, TF32 MMA, inputs pre-rounded.
// 128x128 tile, BK=32, 512 threads, 4-stage cp.async, ldmatrix fragments.
// ---------------------------------------------------------------------------
#define GS 36
#define NTG 32   // K/32
__global__ __launch_bounds__(512, 1)
void gemm_tf32_nt(const float* __restrict__ A, const float* __restrict__ Wb,
                  float* __restrict__ C0, float* __restrict__ C1,
                  float* __restrict__ C2, int ro)
{
    const float* Bw = Wb + (size_t)blockIdx.z * CC * CC;
    float*       C  = (blockIdx.z == 0) ? C0 : (blockIdx.z == 1 ? C1 : C2);

    extern __shared__ float sm[];
    float* As = sm;                   // [4][128][GS]
    float* Bs = sm + 4 * 128 * GS;    // [4][128][GS]
    uint32_t sAu = (uint32_t)__cvta_generic_to_shared(As);
    uint32_t sBu = (uint32_t)__cvta_generic_to_shared(Bs);

    const int tid  = threadIdx.x;
    const int lane = tid & 31;
    const int warp = tid >> 5;
    const int wm   = (warp & 3) * 32;
    const int wn   = (warp >> 2) * 32;

    // ldmatrix per-thread row/col offsets (bytes)
    const int lrow = lane & 15;
    const int lkof = (lane & 16) ? 4 : 0;
    const uint32_t aoff0 = ((wm + lrow)      * GS + lkof) * 4;
    const uint32_t aoff1 = ((wm + 16 + lrow) * GS + lkof) * 4;
    const uint32_t boff0 = ((wn + lrow)      * GS + lkof) * 4;
    const uint32_t boff1 = ((wn + 16 + lrow) * GS + lkof) * 4;

    const float* Abase = A  + (size_t)(blockIdx.y * 128) * CC;
    const float* Bbase = Bw + (size_t)(blockIdx.x * 128) * CC;

    auto load_stage = [&](int kt, int s) {
        #pragma unroll
        for (int i = 0; i < 2; i++) {
            int g = tid + i * 512;
            int row = g >> 3, c16 = g & 7;
            const float* srcA = Abase + (size_t)row * CC + kt * 32 + c16 * 4;
            const float* srcB = Bbase + (size_t)row * CC + kt * 32 + c16 * 4;
            CPA16(sAu + s * (128 * GS * 4) + row * (GS * 4) + c16 * 16, srcA);
            CPA16(sBu + s * (128 * GS * 4) + row * (GS * 4) + c16 * 16, srcB);
        }
        CPCOMMIT();
    };

    load_stage(0, 0);
    load_stage(1, 1);
    load_stage(2, 2);

    float acc[2][4][4];
    #pragma unroll
    for (int i = 0; i < 2; i++)
        #pragma unroll
        for (int j = 0; j < 4; j++)
            #pragma unroll
            for (int k = 0; k < 4; k++) acc[i][j][k] = 0.f;

    for (int kt = 0; kt < NTG; kt++) {
        if (kt <= NTG - 3)      { CPWAIT(2); }
        else if (kt == NTG - 2) { CPWAIT(1); }
        else                    { CPWAIT(0); }
        __syncthreads();

        if (kt + 3 < NTG) load_stage(kt + 3, (kt + 3) & 3);

        const uint32_t AbU = sAu + (kt & 3) * (128 * GS * 4);
        const uint32_t BbU = sBu + (kt & 3) * (128 * GS * 4);

        #pragma unroll
        for (int ks = 0; ks < 4; ks++) {
            uint32_t af[2][4], bf[4][2];
            ldsm_x4(af[0][0], af[0][1], af[0][2], af[0][3], AbU + aoff0 + ks * 32);
            ldsm_x4(af[1][0], af[1][1], af[1][2], af[1][3], AbU + aoff1 + ks * 32);
            // x4 over n16: regs -> (n0-7,k0-3),(n8-15,k0-3),(n0-7,k4-7),(n8-15,k4-7)
            ldsm_x4(bf[0][0], bf[1][0], bf[0][1], bf[1][1], BbU + boff0 + ks * 32);
            ldsm_x4(bf[2][0], bf[3][0], bf[2][1], bf[3][1], BbU + boff1 + ks * 32);
            #pragma unroll
            for (int mt = 0; mt < 2; mt++)
                #pragma unroll
                for (int nt = 0; nt < 4; nt++)
                    mma_tf32(acc[mt][nt], af[mt], bf[nt]);
        }
    }

    #pragma unroll
    for (int mt = 0; mt < 2; mt++) {
        int r0 = blockIdx.y * 128 + wm + mt * 16 + (lane >> 2);
        #pragma unroll
        for (int nt = 0; nt < 4; nt++) {
            int c0 = blockIdx.x * 128 + wn + nt * 8 + (lane & 3) * 2;
            float v0 = acc[mt][nt][0], v1 = acc[mt][nt][1];
            float v2 = acc[mt][nt][2], v3 = acc[mt][nt][3];
            if (ro) { v0 = tf32r(v0); v1 = tf32r(v1); v2 = tf32r(v2); v3 = tf32r(v3); }
            *(float2*)&C[(size_t)r0 * CC + c0]       = make_float2(v0, v1);
            *(float2*)&C[(size_t)(r0 + 8) * CC + c0] = make_float2(v2, v3);
        }
    }
}

// ---------------------------------------------------------------------------
// Kernel A: scores + ALiBi + softmax + attn write. block=(b,h,32q), 512 thr.
// Q fragments in registers; K fragments via ldmatrix.
// ---------------------------------------------------------------------------
#define SSST 1028
#define SQST 68
#define KST  68
#define KBUF (128 * KST)
__global__ __launch_bounds__(512, 1)
void attn_score_kernel(const float* __restrict__ Q, const float* __restrict__ Km,
                       float* __restrict__ attn)
{
    extern __shared__ float sm[];
    float* sS = sm;                      // 32 * 1028
    float* sQ = sS + 32 * SSST;          // 32 * 68
    float* sK = sQ + 32 * SQST;          // 2 * KBUF
    uint32_t sKu = (uint32_t)__cvta_generic_to_shared(sK);

    const int tid  = threadIdx.x;
    const int lane = tid & 31;
    const int warp = tid >> 5;           // 0..15
    const int qb   = blockIdx.x * 32;
    const int h    = blockIdx.y;
    const int b    = blockIdx.z;

    const float scale = 0.125f;
    const float slope = exp2f(-0.5f * (float)(h + 1));

    const int mt = warp & 1;
    const int wn = warp >> 1;

    const int lrow = lane & 15;
    const int lkof = (lane & 16) ? 4 : 0;
    const uint32_t koff = ((wn * 16 + lrow) * KST + lkof) * 4;

    const float* Kb = Km + ((size_t)(b * TT)) * CC + h * DD;

    auto issueK = [&](int c, int buf) {
        const float* base = Kb + (size_t)(c * 128) * CC;
        #pragma unroll
        for (int i = 0; i < 4; i++) {
            int g = tid + i * 512;
            int row = g >> 4, c16 = g & 15;
            CPA16(sKu + buf * (KBUF * 4) + row * (KST * 4) + c16 * 16,
                  base + (size_t)row * CC + c16 * 4);
        }
        CPCOMMIT();
    };

    issueK(0, 0);

    // Q tile [32 x 64] -> sQ
    {
        const float* Qb = Q + ((size_t)(b * TT + qb)) * CC + h * DD;
        int r = tid >> 4, c4 = (tid & 15) << 2;
        *(float4*)(sQ + r * SQST + c4) = *(const float4*)(Qb + (size_t)r * CC + c4);
    }
    __syncthreads();

    // preload Q fragments for all 8 k-steps (loop-invariant across chunks)
    uint32_t aq[8][4];
    {
        int rq = mt * 16 + (lane >> 2);
        #pragma unroll
        for (int ks = 0; ks < 8; ks++) {
            int k0 = ks * 8 + (lane & 3);
            aq[ks][0] = bitsf(sQ[rq * SQST + k0]);
            aq[ks][1] = bitsf(sQ[(rq + 8) * SQST + k0]);
            aq[ks][2] = bitsf(sQ[rq * SQST + k0 + 4]);
            aq[ks][3] = bitsf(sQ[(rq + 8) * SQST + k0 + 4]);
        }
    }

    int buf = 0;
    for (int c = 0; c < 8; c++) {
        if (c + 1 < 8) issueK(c + 1, buf ^ 1);
        if (c < 7) { CPWAIT(1); } else { CPWAIT(0); }
        __syncthreads();

        const uint32_t KU = sKu + buf * (KBUF * 4);
        float cr[2][4];
        #pragma unroll
        for (int nt = 0; nt < 2; nt++)
            #pragma unroll
            for (int i = 0; i < 4; i++) cr[nt][i] = 0.f;

        #pragma unroll
        for (int ks = 0; ks < 8; ks++) {
            uint32_t bf2[2][2];
            ldsm_x4(bf2[0][0], bf2[1][0], bf2[0][1], bf2[1][1], KU + koff + ks * 32);
            mma_tf32(cr[0], aq[ks], bf2[0]);
            mma_tf32(cr[1], aq[ks], bf2[1]);
        }

        const int kc = c * 128;
        #pragma unroll
        for (int nt = 0; nt < 2; nt++) {
            int r0 = mt * 16 + (lane >> 2);
            int cl = wn * 16 + nt * 8 + (lane & 3) * 2;
            float q0 = (float)(qb + r0), q8 = q0 + 8.0f;
            float k0f = (float)(kc + cl), k1f = k0f + 1.0f;
            *(float2*)&sS[r0 * SSST + kc + cl] = make_float2(
                cr[nt][0] * scale - slope * fabsf(q0 - k0f),
                cr[nt][1] * scale - slope * fabsf(q0 - k1f));
            *(float2*)&sS[(r0 + 8) * SSST + kc + cl] = make_float2(
                cr[nt][2] * scale - slope * fabsf(q8 - k0f),
                cr[nt][3] * scale - slope * fabsf(q8 - k1f));
        }
        __syncthreads();
        buf ^= 1;
    }

    // softmax: each warp owns 2 rows; exp values kept in registers
    const size_t attn_base = (((size_t)(b * HH + h)) * TT + qb) * TT;
    #pragma unroll
    for (int rr = 0; rr < 2; rr++) {
        int q = warp * 2 + rr;
        float* row = sS + q * SSST;
        float4 e[8];
        float m = -1e30f;
        #pragma unroll
        for (int it = 0; it < 8; it++) {
            e[it] = *(float4*)(row + it * 128 + lane * 4);
            m = fmaxf(m, fmaxf(fmaxf(e[it].x, e[it].y), fmaxf(e[it].z, e[it].w)));
        }
        #pragma unroll
        for (int off = 16; off; off >>= 1) m = fmaxf(m, __shfl_xor_sync(~0u, m, off));
        float s = 0.f;
        #pragma unroll
        for (int it = 0; it < 8; it++) {
            e[it].x = __expf(e[it].x - m);
            e[it].y = __expf(e[it].y - m);
            e[it].z = __expf(e[it].z - m);
            e[it].w = __expf(e[it].w - m);
            s += (e[it].x + e[it].y) + (e[it].z + e[it].w);
        }
        #pragma unroll
        for (int off = 16; off; off >>= 1) s += __shfl_xor_sync(~0u, s, off);
        float inv = 1.0f / s;
        float* out = attn + attn_base + (size_t)q * TT;
        #pragma unroll
        for (int it = 0; it < 8; it++) {
            float4 v = e[it];
            v.x *= inv; v.y *= inv; v.z *= inv; v.w *= inv;
            *(float4*)(out + it * 128 + lane * 4) = v;
        }
    }
}

// ---------------------------------------------------------------------------
// Kernel B: Y[128x64] = P[128x1024] @ V[1024x64] per (b,h,qtile).
// P fragments via ldmatrix + cvt.rna.tf32. 256 thr, 4-stage cp.async.
// ---------------------------------------------------------------------------
#define PST 36
#define VST 72
#define BSTAGE_F (128 * PST + 32 * VST)   // floats per stage
__global__ __launch_bounds__(256, 2)
void pv_kernel(const float* __restrict__ attn, const float* __restrict__ V,
               float* __restrict__ Y)
{
    extern __shared__ float sm[];
    float* Ps = sm;                                // [4][128][PST]
    float* Vs = sm + 4 * 128 * PST;                // [4][32][VST]
    uint32_t sPu = (uint32_t)__cvta_generic_to_shared(Ps);
    uint32_t sVu = (uint32_t)__cvta_generic_to_shared(Vs);

    const int tid  = threadIdx.x;
    const int lane = tid & 31;
    const int warp = tid >> 5;            // 0..7
    const int qb   = blockIdx.x * 128;
    const int h    = blockIdx.y;
    const int b    = blockIdx.z;

    const int wm = (warp >> 1) * 32;      // 4 row groups of 32
    const int wn = (warp & 1) * 32;       // 2 col groups of 32

    const int lrow = lane & 15;
    const int lkof = (lane & 16) ? 4 : 0;
    const uint32_t poff0 = ((wm + lrow)      * PST + lkof) * 4;
    const uint32_t poff1 = ((wm + 16 + lrow) * PST + lkof) * 4;

    const float* Pb = attn + (((size_t)(b * HH + h)) * TT + qb) * TT;
    const float* Vb = V + ((size_t)(b * TT)) * CC + h * DD;

    auto load_stage = [&](int kt, int s) {
        #pragma unroll
        for (int i = 0; i < 4; i++) {
            int g = tid + i * 256;
            int row = g >> 3, c16 = g & 7;
            CPA16(sPu + s * (128 * PST * 4) + row * (PST * 4) + c16 * 16,
                  Pb + (size_t)row * TT + kt * 32 + c16 * 4);
        }
        #pragma unroll
        for (int i = 0; i < 2; i++) {
            int g = tid + i * 256;
            int row = g >> 4, c16 = g & 15;
            CPA16(sVu + s * (32 * VST * 4) + row * (VST * 4) + c16 * 16,
                  Vb + (size_t)(kt * 32 + row) * CC + c16 * 4);
        }
        CPCOMMIT();
    };

    load_stage(0, 0);
    load_stage(1, 1);
    load_stage(2, 2);

    float acc[2][4][4];
    #pragma unroll
    for (int i = 0; i < 2; i++)
        #pragma unroll
        for (int j = 0; j < 4; j++)
            #pragma unroll
            for (int k = 0; k < 4; k++) acc[i][j][k] = 0.f;

    const int NT2 = 32;
    for (int kt = 0; kt < NT2; kt++) {
        if (kt <= NT2 - 3)      { CPWAIT(2); }
        else if (kt == NT2 - 2) { CPWAIT(1); }
        else                    { CPWAIT(0); }
        __syncthreads();

        if (kt + 3 < NT2) load_stage(kt + 3, (kt + 3) & 3);

        const uint32_t PtU = sPu + (kt & 3) * (128 * PST * 4);
        const float* Vt = Vs + (kt & 3) * (32 * VST);

        #pragma unroll
        for (int ks = 0; ks < 4; ks++) {
            const int k0v = ks * 8;
            uint32_t af[2][4], bf[4][2];
            ldsm_x4(af[0][0], af[0][1], af[0][2], af[0][3], PtU + poff0 + ks * 32);
            ldsm_x4(af[1][0], af[1][1], af[1][2], af[1][3], PtU + poff1 + ks * 32);
            #pragma unroll
            for (int mt2 = 0; mt2 < 2; mt2++)
                #pragma unroll
                for (int i = 0; i < 4; i++)
                    af[mt2][i] = tf32b(__uint_as_float(af[mt2][i]));
            #pragma unroll
            for (int nt = 0; nt < 4; nt++) {
                int n = wn + nt * 8 + (lane >> 2);
                bf[nt][0] = bitsf(Vt[(k0v + (lane & 3)) * VST + n]);
                bf[nt][1] = bitsf(Vt[(k0v + 4 + (lane & 3)) * VST + n]);
            }
            #pragma unroll
            for (int mt2 = 0; mt2 < 2; mt2++)
                #pragma unroll
                for (int nt = 0; nt < 4; nt++)
                    mma_tf32(acc[mt2][nt], af[mt2], bf[nt]);
        }
    }

    // Y store (tf32-rounded: feeds the output projection)
    #pragma unroll
    for (int mt2 = 0; mt2 < 2; mt2++) {
        int r0 = qb + wm + mt2 * 16 + (lane >> 2);
        #pragma unroll
        for (int nt = 0; nt < 4; nt++) {
            int c0 = wn + nt * 8 + (lane & 3) * 2;
            float* y0 = &Y[(size_t)(b * TT + r0) * CC + h * DD + c0];
            float* y1 = &Y[(size_t)(b * TT + r0 + 8) * CC + h * DD + c0];
            *(float2*)y0 = make_float2(tf32r(acc[mt2][nt][0]), tf32r(acc[mt2][nt][1]));
            *(float2*)y1 = make_float2(tf32r(acc[mt2][nt][2]), tf32r(acc[mt2][nt][3]));
        }
    }
}

// ---------------------------------------------------------------------------
// launch: prepass -> QKV proj -> scores/softmax -> PV -> output proj
// d_out = [ y (B*T*C) | attn (B*H*T*T) ]
// ---------------------------------------------------------------------------
extern "C" void kernel_launch(void* const* d_in, const int* in_sizes, int n_in,
                              void* d_out, int out_size)
{
    const float* x  = (const float*)d_in[0];
    const float* Wq = (const float*)d_in[1];
    const float* Wk = (const float*)d_in[2];
    const float* Wv = (const float*)d_in[3];
    const float* Wp = (const float*)d_in[4];

    float* out      = (float*)d_out;
    float* y_out    = out;
    float* attn_out = out + (size_t)BB * TT * CC;

    float *Qp, *Kp, *Vp, *Yp, *Xp, *Wc;
    cudaGetSymbolAddress((void**)&Qp, g_Q);
    cudaGetSymbolAddress((void**)&Kp, g_K);
    cudaGetSymbolAddress((void**)&Vp, g_V);
    cudaGetSymbolAddress((void**)&Yp, g_Y);
    cudaGetSymbolAddress((void**)&Xp, g_X);
    cudaGetSymbolAddress((void**)&Wc, g_W);

    prepass<<<dim3(1024, 5), 256>>>(x, Wq, Wk, Wv, Wp);

    const size_t gemm_smem = (size_t)(8 * 128 * GS) * sizeof(float);  // 147456
    cudaFuncSetAttribute(gemm_tf32_nt,
                         cudaFuncAttributeMaxDynamicSharedMemorySize,
                         (int)gemm_smem);

    dim3 gq(CC / 128, BT / 128, 3);
    gemm_tf32_nt<<<gq, 512, gemm_smem>>>(Xp, Wc, Qp, Kp, Vp, 1);

    const size_t scoreA_smem =
        (size_t)(32 * SSST + 32 * SQST + 2 * KBUF) * sizeof(float);   // 209920
    cudaFuncSetAttribute(attn_score_kernel,
                         cudaFuncAttributeMaxDynamicSharedMemorySize,
                         (int)scoreA_smem);
    attn_score_kernel<<<dim3(TT / 32, HH, BB), 512, scoreA_smem>>>(Qp, Kp, attn_out);

    const size_t pv_smem = (size_t)(4 * BSTAGE_F) * sizeof(float);    // 110592
    cudaFuncSetAttribute(pv_kernel,
                         cudaFuncAttributeMaxDynamicSharedMemorySize,
                         (int)pv_smem);
    pv_kernel<<<dim3(TT / 128, HH, BB), 256, pv_smem>>>(attn_out, Vp, Yp);

    dim3 gp(CC / 128, BT / 128, 1);
    gemm_tf32_nt<<<gp, 512, gemm_smem>>>(Yp, Wc + (size_t)3 * CC * CC,
                                         y_out, y_out, y_out, 0);
}

// round 7
// speedup vs baseline: 6.8850x; 1.5196x over previous
#include <cuda_runtime.h>
#include <cuda_fp16.h>
#include <math.h>
#include <stdint.h>

#define BB   4
#define TT   1024
#define CC   1024
#define HH   16
#define DD   64
#define BT   (BB*TT)          // 4096

// Scratch (allocation-free rule: __device__ globals)
__device__ __half g_Qh[BT * CC];
__device__ __half g_Kh[BT * CC];
__device__ __half g_Vh[BT * CC];
__device__ __half g_Yh[BT * CC];
__device__ __half g_Xh[BT * CC];          // fp16-rounded x
__device__ __half g_Wh[4 * CC * CC];      // fp16-rounded Wq|Wk|Wv|Wp
__device__ __half g_P[(size_t)BB * HH * TT * TT];   // fp16 attention probs

// ---------------------------------------------------------------------------
// helpers
// ---------------------------------------------------------------------------
__device__ __forceinline__ uint2 f4_to_h4(float4 v) {
    __half2 a = __floats2half2_rn(v.x, v.y);
    __half2 b = __floats2half2_rn(v.z, v.w);
    uint2 r;
    r.x = *(uint32_t*)&a;
    r.y = *(uint32_t*)&b;
    return r;
}

__device__ __forceinline__ void mma_f16(float* c, const uint32_t* a, const uint32_t* b) {
    asm volatile(
        "mma.sync.aligned.m16n8k16.row.col.f32.f16.f16.f32 "
        "{%0,%1,%2,%3}, {%4,%5,%6,%7}, {%8,%9}, {%0,%1,%2,%3};"
        : "+f"(c[0]), "+f"(c[1]), "+f"(c[2]), "+f"(c[3])
        : "r"(a[0]), "r"(a[1]), "r"(a[2]), "r"(a[3]), "r"(b[0]), "r"(b[1]));
}

__device__ __forceinline__ void ldsm_x4(uint32_t& r0, uint32_t& r1,
                                        uint32_t& r2, uint32_t& r3, uint32_t addr) {
    asm volatile("ldmatrix.sync.aligned.m8n8.x4.shared.b16 {%0,%1,%2,%3}, [%4];"
                 : "=r"(r0), "=r"(r1), "=r"(r2), "=r"(r3) : "r"(addr));
}
__device__ __forceinline__ void ldsm_x4t(uint32_t& r0, uint32_t& r1,
                                         uint32_t& r2, uint32_t& r3, uint32_t addr) {
    asm volatile("ldmatrix.sync.aligned.m8n8.x4.trans.shared.b16 {%0,%1,%2,%3}, [%4];"
                 : "=r"(r0), "=r"(r1), "=r"(r2), "=r"(r3) : "r"(addr));
}

#define CPA16(dst_u32, src_ptr) \
    asm volatile("cp.async.cg.shared.global [%0], [%1], 16;" \
                 :: "r"(dst_u32), "l"(src_ptr))
#define CPCOMMIT() asm volatile("cp.async.commit_group;")
#define CPWAIT(n)  asm volatile("cp.async.wait_group %0;" :: "n"(n))

// ---------------------------------------------------------------------------
// prepass: fp16-round x -> g_Xh, weights -> g_Wh (concat)
// ---------------------------------------------------------------------------
__global__ void prepass(const float* __restrict__ x,
                        const float* __restrict__ wq, const float* __restrict__ wk,
                        const float* __restrict__ wv, const float* __restrict__ wp)
{
    int which = blockIdx.y;
    const float* src;
    __half* dst;
    int n4;
    if (which == 0) { src = x;  dst = g_Xh; n4 = BT * CC / 4; }
    else {
        src = (which == 1) ? wq : (which == 2) ? wk : (which == 3) ? wv : wp;
        dst = g_Wh + (size_t)(which - 1) * CC * CC;
        n4 = CC * CC / 4;
    }
    for (int i = blockIdx.x * blockDim.x + threadIdx.x; i < n4;
         i += gridDim.x * blockDim.x) {
        float4 v = ((const float4*)src)[i];
        ((uint2*)dst)[i] = f4_to_h4(v);
    }
}

// ---------------------------------------------------------------------------
// C[M,N] = A[M,K] @ W[N,K]^T, FP16 MMA m16n8k16, inputs pre-rounded fp16.
// 128x128 tile, BK=32, 512 threads, 4-stage cp.async, ldmatrix fragments.
// ro=1: write half outputs H0/H1/H2 (per blockIdx.z); ro=0: float C0.
// ---------------------------------------------------------------------------
#define AST 40                   // halfs per row (80 bytes)
#define GSTG (128 * AST * 2)     // stage bytes per array: 10240
#define NTG 32                   // K/32
__global__ __launch_bounds__(512, 1)
void gemm_f16_nt(const __half* __restrict__ A, const __half* __restrict__ Wb,
                 __half* __restrict__ H0, __half* __restrict__ H1,
                 __half* __restrict__ H2, float* __restrict__ C0, int ro)
{
    const __half* Bw = Wb + (size_t)blockIdx.z * CC * CC;
    __half* H = (blockIdx.z == 0) ? H0 : (blockIdx.z == 1 ? H1 : H2);

    extern __shared__ char smraw[];
    uint32_t sAu = (uint32_t)__cvta_generic_to_shared(smraw);
    uint32_t sBu = sAu + 4 * GSTG;

    const int tid  = threadIdx.x;
    const int lane = tid & 31;
    const int warp = tid >> 5;
    const int wm   = (warp & 3) * 32;
    const int wn   = (warp >> 2) * 32;

    const int lrow = lane & 15;
    const int lkof = (lane & 16) ? 8 : 0;     // halfs
    const uint32_t aoff0 = ((wm + lrow)      * AST + lkof) * 2;
    const uint32_t aoff1 = ((wm + 16 + lrow) * AST + lkof) * 2;
    const uint32_t boff0 = ((wn + lrow)      * AST + lkof) * 2;
    const uint32_t boff1 = ((wn + 16 + lrow) * AST + lkof) * 2;

    const __half* Abase = A  + (size_t)(blockIdx.y * 128) * CC;
    const __half* Bbase = Bw + (size_t)(blockIdx.x * 128) * CC;

    auto load_stage = [&](int kt, int s) {
        int row = tid >> 2, seg = tid & 3;               // 512 granules per array
        CPA16(sAu + s * GSTG + row * 80 + seg * 16,
              Abase + (size_t)row * CC + kt * 32 + seg * 8);
        CPA16(sBu + s * GSTG + row * 80 + seg * 16,
              Bbase + (size_t)row * CC + kt * 32 + seg * 8);
        CPCOMMIT();
    };

    load_stage(0, 0);
    load_stage(1, 1);
    load_stage(2, 2);

    float acc[2][4][4];
    #pragma unroll
    for (int i = 0; i < 2; i++)
        #pragma unroll
        for (int j = 0; j < 4; j++)
            #pragma unroll
            for (int k = 0; k < 4; k++) acc[i][j][k] = 0.f;

    for (int kt = 0; kt < NTG; kt++) {
        if (kt <= NTG - 3)      { CPWAIT(2); }
        else if (kt == NTG - 2) { CPWAIT(1); }
        else                    { CPWAIT(0); }
        __syncthreads();

        if (kt + 3 < NTG) load_stage(kt + 3, (kt + 3) & 3);

        const uint32_t AbU = sAu + (kt & 3) * GSTG;
        const uint32_t BbU = sBu + (kt & 3) * GSTG;

        #pragma unroll
        for (int ks = 0; ks < 2; ks++) {                 // 2 x k16
            uint32_t af[2][4], bf[4][2];
            ldsm_x4(af[0][0], af[0][1], af[0][2], af[0][3], AbU + aoff0 + ks * 32);
            ldsm_x4(af[1][0], af[1][1], af[1][2], af[1][3], AbU + aoff1 + ks * 32);
            ldsm_x4(bf[0][0], bf[1][0], bf[0][1], bf[1][1], BbU + boff0 + ks * 32);
            ldsm_x4(bf[2][0], bf[3][0], bf[2][1], bf[3][1], BbU + boff1 + ks * 32);
            #pragma unroll
            for (int mt = 0; mt < 2; mt++)
                #pragma unroll
                for (int nt = 0; nt < 4; nt++)
                    mma_f16(acc[mt][nt], af[mt], bf[nt]);
        }
    }

    #pragma unroll
    for (int mt = 0; mt < 2; mt++) {
        int r0 = blockIdx.y * 128 + wm + mt * 16 + (lane >> 2);
        #pragma unroll
        for (int nt = 0; nt < 4; nt++) {
            int c0 = blockIdx.x * 128 + wn + nt * 8 + (lane & 3) * 2;
            if (ro) {
                __half2 h01 = __floats2half2_rn(acc[mt][nt][0], acc[mt][nt][1]);
                __half2 h23 = __floats2half2_rn(acc[mt][nt][2], acc[mt][nt][3]);
                *(__half2*)&H[(size_t)r0 * CC + c0]       = h01;
                *(__half2*)&H[(size_t)(r0 + 8) * CC + c0] = h23;
            } else {
                *(float2*)&C0[(size_t)r0 * CC + c0] =
                    make_float2(acc[mt][nt][0], acc[mt][nt][1]);
                *(float2*)&C0[(size_t)(r0 + 8) * CC + c0] =
                    make_float2(acc[mt][nt][2], acc[mt][nt][3]);
            }
        }
    }
}

// ---------------------------------------------------------------------------
// Kernel A: scores + ALiBi + softmax; writes attn fp32 (d_out) + P fp16 (g_P).
// block=(b,h,32q), 512 thr. Q fragments in regs; K fragments via ldmatrix.
// ---------------------------------------------------------------------------
#define SSST 1028
#define QST 72
#define KST 72
#define KBUFB (128 * KST * 2)    // stage bytes
__global__ __launch_bounds__(512, 1)
void attn_score_kernel(const __half* __restrict__ Q, const __half* __restrict__ Km,
                       float* __restrict__ attn, __half* __restrict__ Ph)
{
    extern __shared__ char smraw[];
    float*  sS = (float*)smraw;                        // 32*1028 floats
    __half* sQ = (__half*)(smraw + 32 * SSST * 4);     // 32*72 halfs
    char*   sK = smraw + 32 * SSST * 4 + 32 * QST * 2; // 2 * KBUFB
    uint32_t sQu = (uint32_t)__cvta_generic_to_shared(sQ);
    uint32_t sKu = (uint32_t)__cvta_generic_to_shared(sK);

    const int tid  = threadIdx.x;
    const int lane = tid & 31;
    const int warp = tid >> 5;           // 0..15
    const int qb   = blockIdx.x * 32;
    const int h    = blockIdx.y;
    const int b    = blockIdx.z;

    const float scale = 0.125f;
    const float slope = exp2f(-0.5f * (float)(h + 1));

    const int mt = warp & 1;
    const int wn = warp >> 1;

    const int lrow = lane & 15;
    const int lkof = (lane & 16) ? 8 : 0;
    const uint32_t koff = ((wn * 16 + lrow) * KST + lkof) * 2;

    const __half* Kb = Km + ((size_t)(b * TT)) * CC + h * DD;

    auto issueK = [&](int c, int buf) {
        const __half* base = Kb + (size_t)(c * 128) * CC;
        #pragma unroll
        for (int i = 0; i < 2; i++) {
            int g = tid + i * 512;              // 1024 granules
            int row = g >> 3, seg = g & 7;
            CPA16(sKu + buf * KBUFB + row * (KST * 2) + seg * 16,
                  base + (size_t)row * CC + seg * 8);
        }
        CPCOMMIT();
    };

    issueK(0, 0);

    // Q tile [32 x 64] halfs -> sQ
    if (tid < 256) {
        const __half* Qb = Q + ((size_t)(b * TT + qb)) * CC + h * DD;
        int r = tid >> 3, seg = tid & 7;
        *(uint4*)(sQ + r * QST + seg * 8) =
            *(const uint4*)(Qb + (size_t)r * CC + seg * 8);
    }
    __syncthreads();

    // preload Q fragments for all 4 k16-steps (loop-invariant)
    uint32_t aq[4][4];
    {
        uint32_t qoff = sQu + ((mt * 16 + lrow) * QST + lkof) * 2;
        #pragma unroll
        for (int ks = 0; ks < 4; ks++)
            ldsm_x4(aq[ks][0], aq[ks][1], aq[ks][2], aq[ks][3], qoff + ks * 32);
    }

    int buf = 0;
    for (int c = 0; c < 8; c++) {
        if (c + 1 < 8) issueK(c + 1, buf ^ 1);
        if (c < 7) { CPWAIT(1); } else { CPWAIT(0); }
        __syncthreads();

        const uint32_t KU = sKu + buf * KBUFB;
        float cr[2][4];
        #pragma unroll
        for (int nt = 0; nt < 2; nt++)
            #pragma unroll
            for (int i = 0; i < 4; i++) cr[nt][i] = 0.f;

        #pragma unroll
        for (int ks = 0; ks < 4; ks++) {
            uint32_t bf2[2][2];
            ldsm_x4(bf2[0][0], bf2[1][0], bf2[0][1], bf2[1][1], KU + koff + ks * 32);
            mma_f16(cr[0], aq[ks], bf2[0]);
            mma_f16(cr[1], aq[ks], bf2[1]);
        }

        const int kc = c * 128;
        #pragma unroll
        for (int nt = 0; nt < 2; nt++) {
            int r0 = mt * 16 + (lane >> 2);
            int cl = wn * 16 + nt * 8 + (lane & 3) * 2;
            float q0 = (float)(qb + r0), q8 = q0 + 8.0f;
            float k0f = (float)(kc + cl), k1f = k0f + 1.0f;
            *(float2*)&sS[r0 * SSST + kc + cl] = make_float2(
                cr[nt][0] * scale - slope * fabsf(q0 - k0f),
                cr[nt][1] * scale - slope * fabsf(q0 - k1f));
            *(float2*)&sS[(r0 + 8) * SSST + kc + cl] = make_float2(
                cr[nt][2] * scale - slope * fabsf(q8 - k0f),
                cr[nt][3] * scale - slope * fabsf(q8 - k1f));
        }
        __syncthreads();
        buf ^= 1;
    }

    // softmax: each warp owns 2 rows; write attn fp32 + P fp16
    const size_t attn_base = (((size_t)(b * HH + h)) * TT + qb) * TT;
    #pragma unroll
    for (int rr = 0; rr < 2; rr++) {
        int q = warp * 2 + rr;
        float* row = sS + q * SSST;
        float4 e[8];
        float m = -1e30f;
        #pragma unroll
        for (int it = 0; it < 8; it++) {
            e[it] = *(float4*)(row + it * 128 + lane * 4);
            m = fmaxf(m, fmaxf(fmaxf(e[it].x, e[it].y), fmaxf(e[it].z, e[it].w)));
        }
        #pragma unroll
        for (int off = 16; off; off >>= 1) m = fmaxf(m, __shfl_xor_sync(~0u, m, off));
        float s = 0.f;
        #pragma unroll
        for (int it = 0; it < 8; it++) {
            e[it].x = __expf(e[it].x - m);
            e[it].y = __expf(e[it].y - m);
            e[it].z = __expf(e[it].z - m);
            e[it].w = __expf(e[it].w - m);
            s += (e[it].x + e[it].y) + (e[it].z + e[it].w);
        }
        #pragma unroll
        for (int off = 16; off; off >>= 1) s += __shfl_xor_sync(~0u, s, off);
        float inv = 1.0f / s;
        float*  out  = attn + attn_base + (size_t)q * TT;
        __half* outh = Ph + attn_base + (size_t)q * TT;
        #pragma unroll
        for (int it = 0; it < 8; it++) {
            float4 v = e[it];
            v.x *= inv; v.y *= inv; v.z *= inv; v.w *= inv;
            int cx = it * 128 + lane * 4;
            *(float4*)(out + cx) = v;            // fp32 attn output
            *(uint2*)(outh + cx) = f4_to_h4(v);  // fp16 P for PV
        }
    }
}

// ---------------------------------------------------------------------------
// Kernel B: Y[128x64] = P[128x1024] @ V[1024x64] per (b,h,qtile), all fp16.
// 256 thr, 4-stage cp.async, P via ldmatrix, V via ldmatrix.trans.
// ---------------------------------------------------------------------------
#define PST 40
#define VST 72
#define PSTGB (128 * PST * 2)     // 10240
#define VSTGB (32 * VST * 2)      // 4608
__global__ __launch_bounds__(256, 2)
void pv_kernel(const __half* __restrict__ Ph, const __half* __restrict__ V,
               __half* __restrict__ Y)
{
    extern __shared__ char smraw[];
    uint32_t sPu = (uint32_t)__cvta_generic_to_shared(smraw);
    uint32_t sVu = sPu + 4 * PSTGB;

    const int tid  = threadIdx.x;
    const int lane = tid & 31;
    const int warp = tid >> 5;            // 0..7
    const int qb   = blockIdx.x * 128;
    const int h    = blockIdx.y;
    const int b    = blockIdx.z;

    const int wm = (warp >> 1) * 32;
    const int wn = (warp & 1) * 32;

    const int lrow = lane & 15;
    const int lkof = (lane & 16) ? 8 : 0;
    const uint32_t poff0 = ((wm + lrow)      * PST + lkof) * 2;
    const uint32_t poff1 = ((wm + 16 + lrow) * PST + lkof) * 2;
    // V trans-ldmatrix offset: row = k (lane&15), col = wn + ((lane&16)?8:0)
    const uint32_t voff = ((lane & 15) * VST + wn + lkof) * 2;

    const __half* Pb = Ph + (((size_t)(b * HH + h)) * TT + qb) * TT;
    const __half* Vb = V + ((size_t)(b * TT)) * CC + h * DD;

    auto load_stage = [&](int kt, int s) {
        #pragma unroll
        for (int i = 0; i < 2; i++) {
            int g = tid + i * 256;               // 512 P granules
            int row = g >> 2, seg = g & 3;
            CPA16(sPu + s * PSTGB + row * 80 + seg * 16,
                  Pb + (size_t)row * TT + kt * 32 + seg * 8);
        }
        {
            int row = tid >> 3, seg = tid & 7;   // 256 V granules
            CPA16(sVu + s * VSTGB + row * (VST * 2) + seg * 16,
                  Vb + (size_t)(kt * 32 + row) * CC + seg * 8);
        }
        CPCOMMIT();
    };

    load_stage(0, 0);
    load_stage(1, 1);
    load_stage(2, 2);

    float acc[2][4][4];
    #pragma unroll
    for (int i = 0; i < 2; i++)
        #pragma unroll
        for (int j = 0; j < 4; j++)
            #pragma unroll
            for (int k = 0; k < 4; k++) acc[i][j][k] = 0.f;

    const int NT2 = 32;
    for (int kt = 0; kt < NT2; kt++) {
        if (kt <= NT2 - 3)      { CPWAIT(2); }
        else if (kt == NT2 - 2) { CPWAIT(1); }
        else                    { CPWAIT(0); }
        __syncthreads();

        if (kt + 3 < NT2) load_stage(kt + 3, (kt + 3) & 3);

        const uint32_t PtU = sPu + (kt & 3) * PSTGB;
        const uint32_t VtU = sVu + (kt & 3) * VSTGB;

        #pragma unroll
        for (int ks = 0; ks < 2; ks++) {
            uint32_t af[2][4], bf[4][2];
            ldsm_x4(af[0][0], af[0][1], af[0][2], af[0][3], PtU + poff0 + ks * 32);
            ldsm_x4(af[1][0], af[1][1], af[1][2], af[1][3], PtU + poff1 + ks * 32);
            // trans loads: (k0-7,n0-7),(k8-15,n0-7),(k0-7,n8-15),(k8-15,n8-15)
            ldsm_x4t(bf[0][0], bf[0][1], bf[1][0], bf[1][1],
                     VtU + voff + ks * 16 * (VST * 2));
            ldsm_x4t(bf[2][0], bf[2][1], bf[3][0], bf[3][1],
                     VtU + voff + 16 * 2 + ks * 16 * (VST * 2));
            #pragma unroll
            for (int mt2 = 0; mt2 < 2; mt2++)
                #pragma unroll
                for (int nt = 0; nt < 4; nt++)
                    mma_f16(acc[mt2][nt], af[mt2], bf[nt]);
        }
    }

    // Y store (fp16: feeds the output projection)
    #pragma unroll
    for (int mt2 = 0; mt2 < 2; mt2++) {
        int r0 = qb + wm + mt2 * 16 + (lane >> 2);
        #pragma unroll
        for (int nt = 0; nt < 4; nt++) {
            int c0 = wn + nt * 8 + (lane & 3) * 2;
            __half2 h01 = __floats2half2_rn(acc[mt2][nt][0], acc[mt2][nt][1]);
            __half2 h23 = __floats2half2_rn(acc[mt2][nt][2], acc[mt2][nt][3]);
            *(__half2*)&Y[(size_t)(b * TT + r0) * CC + h * DD + c0]       = h01;
            *(__half2*)&Y[(size_t)(b * TT + r0 + 8) * CC + h * DD + c0]   = h23;
        }
    }
}

// ---------------------------------------------------------------------------
// launch: prepass -> QKV proj -> scores/softmax -> PV -> output proj
// d_out = [ y (B*T*C) fp32 | attn (B*H*T*T) fp32 ]
// ---------------------------------------------------------------------------
extern "C" void kernel_launch(void* const* d_in, const int* in_sizes, int n_in,
                              void* d_out, int out_size)
{
    const float* x  = (const float*)d_in[0];
    const float* Wq = (const float*)d_in[1];
    const float* Wk = (const float*)d_in[2];
    const float* Wv = (const float*)d_in[3];
    const float* Wp = (const float*)d_in[4];

    float* out      = (float*)d_out;
    float* y_out    = out;
    float* attn_out = out + (size_t)BB * TT * CC;

    __half *Qh, *Kh, *Vh, *Yh, *Xh, *Wh, *Pp;
    cudaGetSymbolAddress((void**)&Qh, g_Qh);
    cudaGetSymbolAddress((void**)&Kh, g_Kh);
    cudaGetSymbolAddress((void**)&Vh, g_Vh);
    cudaGetSymbolAddress((void**)&Yh, g_Yh);
    cudaGetSymbolAddress((void**)&Xh, g_Xh);
    cudaGetSymbolAddress((void**)&Wh, g_Wh);
    cudaGetSymbolAddress((void**)&Pp, g_P);

    prepass<<<dim3(1024, 5), 256>>>(x, Wq, Wk, Wv, Wp);

    const size_t gemm_smem = (size_t)8 * GSTG;                        // 81920
    cudaFuncSetAttribute(gemm_f16_nt,
                         cudaFuncAttributeMaxDynamicSharedMemorySize,
                         (int)gemm_smem);

    dim3 gq(CC / 128, BT / 128, 3);
    gemm_f16_nt<<<gq, 512, gemm_smem>>>(Xh, Wh, Qh, Kh, Vh, nullptr, 1);

    const size_t scoreA_smem =
        (size_t)32 * SSST * 4 + 32 * QST * 2 + 2 * KBUFB;             // 173056
    cudaFuncSetAttribute(attn_score_kernel,
                         cudaFuncAttributeMaxDynamicSharedMemorySize,
                         (int)scoreA_smem);
    attn_score_kernel<<<dim3(TT / 32, HH, BB), 512, scoreA_smem>>>(
        Qh, Kh, attn_out, Pp);

    const size_t pv_smem = (size_t)4 * (PSTGB + VSTGB);               // 59392
    cudaFuncSetAttribute(pv_kernel,
                         cudaFuncAttributeMaxDynamicSharedMemorySize,
                         (int)pv_smem);
    pv_kernel<<<dim3(TT / 128, HH, BB), 256, pv_smem>>>(Pp, Vh, Yh);

    dim3 gp(CC / 128, BT / 128, 1);
    gemm_f16_nt<<<gp, 512, gemm_smem>>>(Yh, Wh + (size_t)3 * CC * CC,
                                        nullptr, nullptr, nullptr, y_out, 0);
}